// round 1
// baseline (speedup 1.0000x reference)
#include <cuda_runtime.h>

#define BATCH 4
#define SEQ   4096
#define DIM   1024
#define HS    64
#define NQKV  192
#define SCALE 0.125f

// Scratch (allocation-free rule: __device__ globals)
__device__ float g_q[BATCH * SEQ * HS];
__device__ float g_k[BATCH * SEQ * HS];
__device__ float g_v[BATCH * SEQ * HS];
__device__ float g_maskadd[BATCH * SEQ];

// ---------------------------------------------------------------------------
// Mask conversion with dtype auto-detect.
// The reference's attn_mask is jnp.bool_; the harness may materialize it as
// 1-byte bool, int32 0/1, or float32 0.0/1.0. Detect via exact integer
// compares on the first 64 words (safe to read under every interpretation:
// min buffer = 16KB). If every word is in {0, 1, 0x3f800000} the data is
// 4-byte (i32 or f32) and "word != 0" is the truth value under both; else
// it is 1-byte bool.
// ---------------------------------------------------------------------------
__global__ void __launch_bounds__(256) mask_kernel(const unsigned char* __restrict__ raw) {
    __shared__ int not_word;
    const int tid = threadIdx.x;
    if (tid == 0) not_word = 0;
    __syncthreads();
    if (tid < 64) {
        unsigned int w = ((const unsigned int*)raw)[tid];
        if (w != 0u && w != 1u && w != 0x3f800000u) atomicOr(&not_word, 1);
    }
    __syncthreads();
    const int i = blockIdx.x * 256 + tid;
    bool on;
    if (!not_word) on = (((const unsigned int*)raw)[i] != 0u);
    else           on = (raw[i] != 0);
    g_maskadd[i] = on ? 0.0f : -1e30f;
}

// ---------------------------------------------------------------------------
// QKV projection: (16384 x 1024) @ (1024 x 192) -> q/k/v each (16384 x 64)
// BM=64, BN=64 (one of q/k/v per blockIdx.x), BK=32, 256 threads, 4x4 microtile
// ---------------------------------------------------------------------------
__global__ void __launch_bounds__(256) qkv_kernel(const float* __restrict__ x,
                                                  const float* __restrict__ W) {
    __shared__ float As[64][32];
    __shared__ float Bs[32][64];
    const int tid = threadIdx.x;
    const int tx = tid & 15, ty = tid >> 4;
    const int m0 = blockIdx.y << 6;
    const int sect = blockIdx.x;          // 0:q 1:k 2:v
    const int n0 = sect * 64;

    float acc[4][4] = {};

    for (int kt = 0; kt < DIM; kt += 32) {
#pragma unroll
        for (int i = 0; i < 2; i++) {
            int idx = tid + i * 256;
            int r = idx >> 3, c4 = idx & 7;
            *(float4*)&As[r][c4 * 4] =
                *(const float4*)&x[(size_t)(m0 + r) * DIM + kt + c4 * 4];
        }
#pragma unroll
        for (int i = 0; i < 2; i++) {
            int idx = tid + i * 256;
            int r = idx >> 4, c4 = idx & 15;
            *(float4*)&Bs[r][c4 * 4] =
                *(const float4*)&W[(size_t)(kt + r) * NQKV + n0 + c4 * 4];
        }
        __syncthreads();
#pragma unroll
        for (int kk = 0; kk < 32; kk++) {
            float a0 = As[ty * 4 + 0][kk];
            float a1 = As[ty * 4 + 1][kk];
            float a2 = As[ty * 4 + 2][kk];
            float a3 = As[ty * 4 + 3][kk];
            float4 b = *(float4*)&Bs[kk][tx * 4];
            acc[0][0] += a0 * b.x; acc[0][1] += a0 * b.y; acc[0][2] += a0 * b.z; acc[0][3] += a0 * b.w;
            acc[1][0] += a1 * b.x; acc[1][1] += a1 * b.y; acc[1][2] += a1 * b.z; acc[1][3] += a1 * b.w;
            acc[2][0] += a2 * b.x; acc[2][1] += a2 * b.y; acc[2][2] += a2 * b.z; acc[2][3] += a2 * b.w;
            acc[3][0] += a3 * b.x; acc[3][1] += a3 * b.y; acc[3][2] += a3 * b.z; acc[3][3] += a3 * b.w;
        }
        __syncthreads();
    }

    float* outp = (sect == 0) ? g_q : (sect == 1) ? g_k : g_v;
#pragma unroll
    for (int i = 0; i < 4; i++) {
        float4 r;
        r.x = acc[i][0]; r.y = acc[i][1]; r.z = acc[i][2]; r.w = acc[i][3];
        *(float4*)&outp[(size_t)(m0 + ty * 4 + i) * HS + tx * 4] = r;
    }
}

// ---------------------------------------------------------------------------
// Flash attention: per block 64 queries, stream 64-key tiles, online softmax.
// Smem layout (dynamic, ~65 KB):
//   Qts[d][row]  (dim-major, pre-scaled)    4096 floats
//   Kts[d][key]  (dim-major)                4096 floats
//   Vs [key][d]                             4096 floats
//   Ps [row][key] stride 68 (pad vs banks)  4352 floats
//   Madd[64]
// ---------------------------------------------------------------------------
#define PS_STRIDE 68
#define ATTN_SMEM_FLOATS (4096 * 3 + 64 * PS_STRIDE + 64)

__global__ void __launch_bounds__(256) attn_kernel(float* __restrict__ out) {
    extern __shared__ float sm[];
    float (*Qts)[64]        = (float(*)[64])sm;
    float (*Kts)[64]        = (float(*)[64])(sm + 4096);
    float (*Vs)[64]         = (float(*)[64])(sm + 8192);
    float (*Ps)[PS_STRIDE]  = (float(*)[PS_STRIDE])(sm + 12288);
    float* Madd             = sm + 12288 + 64 * PS_STRIDE;

    const int tid = threadIdx.x;
    const int tx = tid & 15, ty = tid >> 4;
    const int b  = blockIdx.y;
    const int q0 = blockIdx.x << 6;

    const float* qb = g_q + ((size_t)b * SEQ + q0) * HS;
    const float* kb = g_k + (size_t)b * SEQ * HS;
    const float* vb = g_v + (size_t)b * SEQ * HS;
    const float* mb = g_maskadd + (size_t)b * SEQ;

    // Load Q tile transposed (dim-major), pre-scaled by 1/sqrt(hs)
    {
        int r  = tid >> 2;
        int d0 = (tid & 3) << 4;
#pragma unroll
        for (int i = 0; i < 4; i++) {
            float4 v4 = *(const float4*)&qb[(size_t)r * HS + d0 + i * 4];
            Qts[d0 + i * 4 + 0][r] = v4.x * SCALE;
            Qts[d0 + i * 4 + 1][r] = v4.y * SCALE;
            Qts[d0 + i * 4 + 2][r] = v4.z * SCALE;
            Qts[d0 + i * 4 + 3][r] = v4.w * SCALE;
        }
    }

    float o[4][4] = {};
    float m_i[4], l_i[4];
#pragma unroll
    for (int i = 0; i < 4; i++) { m_i[i] = -1e38f; l_i[i] = 0.0f; }

    for (int k0 = 0; k0 < SEQ; k0 += 64) {
        __syncthreads();  // previous PV reads done before overwriting tiles
        {
            int r  = tid >> 2;
            int d0 = (tid & 3) << 4;
#pragma unroll
            for (int i = 0; i < 4; i++) {
                float4 kv = *(const float4*)&kb[(size_t)(k0 + r) * HS + d0 + i * 4];
                Kts[d0 + i * 4 + 0][r] = kv.x;
                Kts[d0 + i * 4 + 1][r] = kv.y;
                Kts[d0 + i * 4 + 2][r] = kv.z;
                Kts[d0 + i * 4 + 3][r] = kv.w;
                *(float4*)&Vs[r][d0 + i * 4] =
                    *(const float4*)&vb[(size_t)(k0 + r) * HS + d0 + i * 4];
            }
            if (tid < 64) Madd[tid] = mb[k0 + tid];
        }
        __syncthreads();

        // S = Q @ K^T  (4x4 per thread)
        float s[4][4] = {};
#pragma unroll 16
        for (int d = 0; d < 64; d++) {
            float4 a  = *(float4*)&Qts[d][ty << 2];
            float4 bq = *(float4*)&Kts[d][tx << 2];
            s[0][0] += a.x * bq.x; s[0][1] += a.x * bq.y; s[0][2] += a.x * bq.z; s[0][3] += a.x * bq.w;
            s[1][0] += a.y * bq.x; s[1][1] += a.y * bq.y; s[1][2] += a.y * bq.z; s[1][3] += a.y * bq.w;
            s[2][0] += a.z * bq.x; s[2][1] += a.z * bq.y; s[2][2] += a.z * bq.z; s[2][3] += a.z * bq.w;
            s[3][0] += a.w * bq.x; s[3][1] += a.w * bq.y; s[3][2] += a.w * bq.z; s[3][3] += a.w * bq.w;
        }

        float madd[4];
#pragma unroll
        for (int j = 0; j < 4; j++) madd[j] = Madd[(tx << 2) + j];

#pragma unroll
        for (int i = 0; i < 4; i++) {
            s[i][0] += madd[0]; s[i][1] += madd[1];
            s[i][2] += madd[2]; s[i][3] += madd[3];
            float mx = fmaxf(fmaxf(s[i][0], s[i][1]), fmaxf(s[i][2], s[i][3]));
#pragma unroll
            for (int off = 8; off; off >>= 1)
                mx = fmaxf(mx, __shfl_xor_sync(0xffffffffu, mx, off, 16));
            float mnew = fmaxf(m_i[i], mx);
            float corr = __expf(m_i[i] - mnew);
            float p0 = __expf(s[i][0] - mnew);
            float p1 = __expf(s[i][1] - mnew);
            float p2 = __expf(s[i][2] - mnew);
            float p3 = __expf(s[i][3] - mnew);
            float4 pv; pv.x = p0; pv.y = p1; pv.z = p2; pv.w = p3;
            *(float4*)&Ps[(ty << 2) + i][tx << 2] = pv;
            float rs = (p0 + p1) + (p2 + p3);
#pragma unroll
            for (int off = 8; off; off >>= 1)
                rs += __shfl_xor_sync(0xffffffffu, rs, off, 16);
            l_i[i] = l_i[i] * corr + rs;
            m_i[i] = mnew;
            o[i][0] *= corr; o[i][1] *= corr; o[i][2] *= corr; o[i][3] *= corr;
        }
        __syncthreads();

        // O += P @ V
#pragma unroll 16
        for (int kk = 0; kk < 64; kk++) {
            float4 vv = *(float4*)&Vs[kk][tx << 2];
            float p0 = Ps[(ty << 2) + 0][kk];
            float p1 = Ps[(ty << 2) + 1][kk];
            float p2 = Ps[(ty << 2) + 2][kk];
            float p3 = Ps[(ty << 2) + 3][kk];
            o[0][0] += p0 * vv.x; o[0][1] += p0 * vv.y; o[0][2] += p0 * vv.z; o[0][3] += p0 * vv.w;
            o[1][0] += p1 * vv.x; o[1][1] += p1 * vv.y; o[1][2] += p1 * vv.z; o[1][3] += p1 * vv.w;
            o[2][0] += p2 * vv.x; o[2][1] += p2 * vv.y; o[2][2] += p2 * vv.z; o[2][3] += p2 * vv.w;
            o[3][0] += p3 * vv.x; o[3][1] += p3 * vv.y; o[3][2] += p3 * vv.z; o[3][3] += p3 * vv.w;
        }
    }

    // Epilogue: normalize by l and store
#pragma unroll
    for (int i = 0; i < 4; i++) {
        float inv = 1.0f / l_i[i];
        float4 r;
        r.x = o[i][0] * inv; r.y = o[i][1] * inv;
        r.z = o[i][2] * inv; r.w = o[i][3] * inv;
        *(float4*)&out[((size_t)b * SEQ + q0 + (ty << 2) + i) * HS + (tx << 2)] = r;
    }
}

extern "C" void kernel_launch(void* const* d_in, const int* in_sizes, int n_in,
                              void* d_out, int out_size) {
    const float*         x    = (const float*)d_in[0];
    const unsigned char* mask = (const unsigned char*)d_in[1];
    const float*         W    = (const float*)d_in[2];
    float*               out  = (float*)d_out;
    (void)in_sizes; (void)n_in; (void)out_size;

    mask_kernel<<<(BATCH * SEQ) / 256, 256>>>(mask);
    qkv_kernel<<<dim3(3, (BATCH * SEQ) / 64), 256>>>(x, W);

    const int attn_smem = ATTN_SMEM_FLOATS * (int)sizeof(float);
    cudaFuncSetAttribute(attn_kernel, cudaFuncAttributeMaxDynamicSharedMemorySize, attn_smem);
    attn_kernel<<<dim3(SEQ / 64, BATCH), 256, attn_smem>>>(out);
}

// round 2
// speedup vs baseline: 1.0588x; 1.0588x over previous
#include <cuda_runtime.h>

#define BATCH 4
#define SEQ   4096
#define DIM   1024
#define HS    64
#define NQKV  192
#define SCALE 0.125f

// Scratch (allocation-free rule: __device__ globals)
__device__ float g_q[BATCH * SEQ * HS];
__device__ float g_k[BATCH * SEQ * HS];
__device__ float g_v[BATCH * SEQ * HS];
__device__ float g_maskadd[BATCH * SEQ];

// ---------------------------------------------------------------------------
// Mask conversion with dtype auto-detect.
// The reference's attn_mask is jnp.bool_; the harness may materialize it as
// 1-byte bool, int32 0/1, or float32 0.0/1.0. Detect via exact integer
// compares on the first 64 words (safe to read under every interpretation:
// min buffer = 16KB). If every word is in {0, 1, 0x3f800000} the data is
// 4-byte (i32 or f32) and "word != 0" is the truth value under both; else
// it is 1-byte bool.
// ---------------------------------------------------------------------------
__global__ void __launch_bounds__(256) mask_kernel(const unsigned char* __restrict__ raw) {
    __shared__ int not_word;
    const int tid = threadIdx.x;
    if (tid == 0) not_word = 0;
    __syncthreads();
    if (tid < 64) {
        unsigned int w = ((const unsigned int*)raw)[tid];
        if (w != 0u && w != 1u && w != 0x3f800000u) atomicOr(&not_word, 1);
    }
    __syncthreads();
    const int i = blockIdx.x * 256 + tid;
    bool on;
    if (!not_word) on = (((const unsigned int*)raw)[i] != 0u);
    else           on = (raw[i] != 0);
    g_maskadd[i] = on ? 0.0f : -1e30f;
}

// ---------------------------------------------------------------------------
// QKV projection: (16384 x 1024) @ (1024 x 192) -> q/k/v each (16384 x 64)
// BM=64, BN=64 (one of q/k/v per blockIdx.x), BK=32, 256 threads, 4x4 microtile
// ---------------------------------------------------------------------------
__global__ void __launch_bounds__(256) qkv_kernel(const float* __restrict__ x,
                                                  const float* __restrict__ W) {
    __shared__ float As[64][32];
    __shared__ float Bs[32][64];
    const int tid = threadIdx.x;
    const int tx = tid & 15, ty = tid >> 4;
    const int m0 = blockIdx.y << 6;
    const int sect = blockIdx.x;          // 0:q 1:k 2:v
    const int n0 = sect * 64;

    float acc[4][4] = {};

    for (int kt = 0; kt < DIM; kt += 32) {
#pragma unroll
        for (int i = 0; i < 2; i++) {
            int idx = tid + i * 256;
            int r = idx >> 3, c4 = idx & 7;
            *(float4*)&As[r][c4 * 4] =
                *(const float4*)&x[(size_t)(m0 + r) * DIM + kt + c4 * 4];
        }
#pragma unroll
        for (int i = 0; i < 2; i++) {
            int idx = tid + i * 256;
            int r = idx >> 4, c4 = idx & 15;
            *(float4*)&Bs[r][c4 * 4] =
                *(const float4*)&W[(size_t)(kt + r) * NQKV + n0 + c4 * 4];
        }
        __syncthreads();
#pragma unroll
        for (int kk = 0; kk < 32; kk++) {
            float a0 = As[ty * 4 + 0][kk];
            float a1 = As[ty * 4 + 1][kk];
            float a2 = As[ty * 4 + 2][kk];
            float a3 = As[ty * 4 + 3][kk];
            float4 b = *(float4*)&Bs[kk][tx * 4];
            acc[0][0] += a0 * b.x; acc[0][1] += a0 * b.y; acc[0][2] += a0 * b.z; acc[0][3] += a0 * b.w;
            acc[1][0] += a1 * b.x; acc[1][1] += a1 * b.y; acc[1][2] += a1 * b.z; acc[1][3] += a1 * b.w;
            acc[2][0] += a2 * b.x; acc[2][1] += a2 * b.y; acc[2][2] += a2 * b.z; acc[2][3] += a2 * b.w;
            acc[3][0] += a3 * b.x; acc[3][1] += a3 * b.y; acc[3][2] += a3 * b.z; acc[3][3] += a3 * b.w;
        }
        __syncthreads();
    }

    float* outp = (sect == 0) ? g_q : (sect == 1) ? g_k : g_v;
#pragma unroll
    for (int i = 0; i < 4; i++) {
        float4 r;
        r.x = acc[i][0]; r.y = acc[i][1]; r.z = acc[i][2]; r.w = acc[i][3];
        *(float4*)&outp[(size_t)(m0 + ty * 4 + i) * HS + tx * 4] = r;
    }
}

// ---------------------------------------------------------------------------
// Flash attention: per block 64 queries, stream 64-key tiles, online softmax.
// Smem layout (dynamic, ~65 KB):
//   Qts[d][row]  (dim-major, pre-scaled)    4096 floats
//   Kts[d][key]  (dim-major)                4096 floats
//   Vs [key][d]                             4096 floats
//   Ps [row][key] stride 68 (pad vs banks)  4352 floats
//   Madd[64]
// ---------------------------------------------------------------------------
#define PS_STRIDE 68
#define ATTN_SMEM_FLOATS (4096 * 3 + 64 * PS_STRIDE + 64)

__global__ void __launch_bounds__(256) attn_kernel(float* __restrict__ out) {
    extern __shared__ float sm[];
    float (*Qts)[64]        = (float(*)[64])sm;
    float (*Kts)[64]        = (float(*)[64])(sm + 4096);
    float (*Vs)[64]         = (float(*)[64])(sm + 8192);
    float (*Ps)[PS_STRIDE]  = (float(*)[PS_STRIDE])(sm + 12288);
    float* Madd             = sm + 12288 + 64 * PS_STRIDE;

    const int tid = threadIdx.x;
    const int tx = tid & 15, ty = tid >> 4;
    const int b  = blockIdx.y;
    const int q0 = blockIdx.x << 6;

    const float* qb = g_q + ((size_t)b * SEQ + q0) * HS;
    const float* kb = g_k + (size_t)b * SEQ * HS;
    const float* vb = g_v + (size_t)b * SEQ * HS;
    const float* mb = g_maskadd + (size_t)b * SEQ;

    // Load Q tile transposed (dim-major), pre-scaled by 1/sqrt(hs)
    {
        int r  = tid >> 2;
        int d0 = (tid & 3) << 4;
#pragma unroll
        for (int i = 0; i < 4; i++) {
            float4 v4 = *(const float4*)&qb[(size_t)r * HS + d0 + i * 4];
            Qts[d0 + i * 4 + 0][r] = v4.x * SCALE;
            Qts[d0 + i * 4 + 1][r] = v4.y * SCALE;
            Qts[d0 + i * 4 + 2][r] = v4.z * SCALE;
            Qts[d0 + i * 4 + 3][r] = v4.w * SCALE;
        }
    }

    float o[4][4] = {};
    float m_i[4], l_i[4];
#pragma unroll
    for (int i = 0; i < 4; i++) { m_i[i] = -1e38f; l_i[i] = 0.0f; }

    for (int k0 = 0; k0 < SEQ; k0 += 64) {
        __syncthreads();  // previous PV reads done before overwriting tiles
        {
            int r  = tid >> 2;
            int d0 = (tid & 3) << 4;
#pragma unroll
            for (int i = 0; i < 4; i++) {
                float4 kv = *(const float4*)&kb[(size_t)(k0 + r) * HS + d0 + i * 4];
                Kts[d0 + i * 4 + 0][r] = kv.x;
                Kts[d0 + i * 4 + 1][r] = kv.y;
                Kts[d0 + i * 4 + 2][r] = kv.z;
                Kts[d0 + i * 4 + 3][r] = kv.w;
                *(float4*)&Vs[r][d0 + i * 4] =
                    *(const float4*)&vb[(size_t)(k0 + r) * HS + d0 + i * 4];
            }
            if (tid < 64) Madd[tid] = mb[k0 + tid];
        }
        __syncthreads();

        // S = Q @ K^T  (4x4 per thread)
        float s[4][4] = {};
#pragma unroll 16
        for (int d = 0; d < 64; d++) {
            float4 a  = *(float4*)&Qts[d][ty << 2];
            float4 bq = *(float4*)&Kts[d][tx << 2];
            s[0][0] += a.x * bq.x; s[0][1] += a.x * bq.y; s[0][2] += a.x * bq.z; s[0][3] += a.x * bq.w;
            s[1][0] += a.y * bq.x; s[1][1] += a.y * bq.y; s[1][2] += a.y * bq.z; s[1][3] += a.y * bq.w;
            s[2][0] += a.z * bq.x; s[2][1] += a.z * bq.y; s[2][2] += a.z * bq.z; s[2][3] += a.z * bq.w;
            s[3][0] += a.w * bq.x; s[3][1] += a.w * bq.y; s[3][2] += a.w * bq.z; s[3][3] += a.w * bq.w;
        }

        float madd[4];
#pragma unroll
        for (int j = 0; j < 4; j++) madd[j] = Madd[(tx << 2) + j];

#pragma unroll
        for (int i = 0; i < 4; i++) {
            s[i][0] += madd[0]; s[i][1] += madd[1];
            s[i][2] += madd[2]; s[i][3] += madd[3];
            float mx = fmaxf(fmaxf(s[i][0], s[i][1]), fmaxf(s[i][2], s[i][3]));
#pragma unroll
            for (int off = 8; off; off >>= 1)
                mx = fmaxf(mx, __shfl_xor_sync(0xffffffffu, mx, off, 16));
            float mnew = fmaxf(m_i[i], mx);
            float corr = __expf(m_i[i] - mnew);
            float p0 = __expf(s[i][0] - mnew);
            float p1 = __expf(s[i][1] - mnew);
            float p2 = __expf(s[i][2] - mnew);
            float p3 = __expf(s[i][3] - mnew);
            float4 pv; pv.x = p0; pv.y = p1; pv.z = p2; pv.w = p3;
            *(float4*)&Ps[(ty << 2) + i][tx << 2] = pv;
            float rs = (p0 + p1) + (p2 + p3);
#pragma unroll
            for (int off = 8; off; off >>= 1)
                rs += __shfl_xor_sync(0xffffffffu, rs, off, 16);
            l_i[i] = l_i[i] * corr + rs;
            m_i[i] = mnew;
            o[i][0] *= corr; o[i][1] *= corr; o[i][2] *= corr; o[i][3] *= corr;
        }
        __syncthreads();

        // O += P @ V
#pragma unroll 16
        for (int kk = 0; kk < 64; kk++) {
            float4 vv = *(float4*)&Vs[kk][tx << 2];
            float p0 = Ps[(ty << 2) + 0][kk];
            float p1 = Ps[(ty << 2) + 1][kk];
            float p2 = Ps[(ty << 2) + 2][kk];
            float p3 = Ps[(ty << 2) + 3][kk];
            o[0][0] += p0 * vv.x; o[0][1] += p0 * vv.y; o[0][2] += p0 * vv.z; o[0][3] += p0 * vv.w;
            o[1][0] += p1 * vv.x; o[1][1] += p1 * vv.y; o[1][2] += p1 * vv.z; o[1][3] += p1 * vv.w;
            o[2][0] += p2 * vv.x; o[2][1] += p2 * vv.y; o[2][2] += p2 * vv.z; o[2][3] += p2 * vv.w;
            o[3][0] += p3 * vv.x; o[3][1] += p3 * vv.y; o[3][2] += p3 * vv.z; o[3][3] += p3 * vv.w;
        }
    }

    // Epilogue: normalize by l and store
#pragma unroll
    for (int i = 0; i < 4; i++) {
        float inv = 1.0f / l_i[i];
        float4 r;
        r.x = o[i][0] * inv; r.y = o[i][1] * inv;
        r.z = o[i][2] * inv; r.w = o[i][3] * inv;
        *(float4*)&out[((size_t)b * SEQ + q0 + (ty << 2) + i) * HS + (tx << 2)] = r;
    }
}

extern "C" void kernel_launch(void* const* d_in, const int* in_sizes, int n_in,
                              void* d_out, int out_size) {
    const float*         x    = (const float*)d_in[0];
    const unsigned char* mask = (const unsigned char*)d_in[1];
    const float*         W    = (const float*)d_in[2];
    float*               out  = (float*)d_out;
    (void)in_sizes; (void)n_in; (void)out_size;

    mask_kernel<<<(BATCH * SEQ) / 256, 256>>>(mask);
    qkv_kernel<<<dim3(3, (BATCH * SEQ) / 64), 256>>>(x, W);

    const int attn_smem = ATTN_SMEM_FLOATS * (int)sizeof(float);
    cudaFuncSetAttribute(attn_kernel, cudaFuncAttributeMaxDynamicSharedMemorySize, attn_smem);
    attn_kernel<<<dim3(SEQ / 64, BATCH), 256, attn_smem>>>(out);
}

// round 3
// speedup vs baseline: 1.0597x; 1.0008x over previous
#include <cuda_runtime.h>

#define BATCH 4
#define SEQ   4096
#define DIM   1024
#define HS    64
#define NQKV  192
#define SCALE 0.125f

// Scratch (allocation-free rule: __device__ globals)
__device__ float g_q[BATCH * SEQ * HS];
__device__ float g_k[BATCH * SEQ * HS];
__device__ float g_v[BATCH * SEQ * HS];
__device__ float g_maskadd[BATCH * SEQ];

// ---------------------------------------------------------------------------
// Mask conversion with dtype auto-detect.
// The reference's attn_mask is jnp.bool_; the harness may materialize it as
// 1-byte bool, int32 0/1, or float32 0.0/1.0. Detect via exact integer
// compares on the first 64 words (safe to read under every interpretation:
// min buffer = 16KB). If every word is in {0, 1, 0x3f800000} the data is
// 4-byte (i32 or f32) and "word != 0" is the truth value under both; else
// it is 1-byte bool.
// ---------------------------------------------------------------------------
__global__ void __launch_bounds__(256) mask_kernel(const unsigned char* __restrict__ raw) {
    __shared__ int not_word;
    const int tid = threadIdx.x;
    if (tid == 0) not_word = 0;
    __syncthreads();
    if (tid < 64) {
        unsigned int w = ((const unsigned int*)raw)[tid];
        if (w != 0u && w != 1u && w != 0x3f800000u) atomicOr(&not_word, 1);
    }
    __syncthreads();
    const int i = blockIdx.x * 256 + tid;
    bool on;
    if (!not_word) on = (((const unsigned int*)raw)[i] != 0u);
    else           on = (raw[i] != 0);
    g_maskadd[i] = on ? 0.0f : -1e30f;
}

// ---------------------------------------------------------------------------
// QKV projection: (16384 x 1024) @ (1024 x 192) -> q/k/v each (16384 x 64)
// BM=64, BN=64 (one of q/k/v per blockIdx.x), BK=32, 256 threads, 4x4 microtile
// ---------------------------------------------------------------------------
__global__ void __launch_bounds__(256) qkv_kernel(const float* __restrict__ x,
                                                  const float* __restrict__ W) {
    __shared__ float As[64][32];
    __shared__ float Bs[32][64];
    const int tid = threadIdx.x;
    const int tx = tid & 15, ty = tid >> 4;
    const int m0 = blockIdx.y << 6;
    const int sect = blockIdx.x;          // 0:q 1:k 2:v
    const int n0 = sect * 64;

    float acc[4][4] = {};

    for (int kt = 0; kt < DIM; kt += 32) {
#pragma unroll
        for (int i = 0; i < 2; i++) {
            int idx = tid + i * 256;
            int r = idx >> 3, c4 = idx & 7;
            *(float4*)&As[r][c4 * 4] =
                *(const float4*)&x[(size_t)(m0 + r) * DIM + kt + c4 * 4];
        }
#pragma unroll
        for (int i = 0; i < 2; i++) {
            int idx = tid + i * 256;
            int r = idx >> 4, c4 = idx & 15;
            *(float4*)&Bs[r][c4 * 4] =
                *(const float4*)&W[(size_t)(kt + r) * NQKV + n0 + c4 * 4];
        }
        __syncthreads();
#pragma unroll
        for (int kk = 0; kk < 32; kk++) {
            float a0 = As[ty * 4 + 0][kk];
            float a1 = As[ty * 4 + 1][kk];
            float a2 = As[ty * 4 + 2][kk];
            float a3 = As[ty * 4 + 3][kk];
            float4 b = *(float4*)&Bs[kk][tx * 4];
            acc[0][0] += a0 * b.x; acc[0][1] += a0 * b.y; acc[0][2] += a0 * b.z; acc[0][3] += a0 * b.w;
            acc[1][0] += a1 * b.x; acc[1][1] += a1 * b.y; acc[1][2] += a1 * b.z; acc[1][3] += a1 * b.w;
            acc[2][0] += a2 * b.x; acc[2][1] += a2 * b.y; acc[2][2] += a2 * b.z; acc[2][3] += a2 * b.w;
            acc[3][0] += a3 * b.x; acc[3][1] += a3 * b.y; acc[3][2] += a3 * b.z; acc[3][3] += a3 * b.w;
        }
        __syncthreads();
    }

    float* outp = (sect == 0) ? g_q : (sect == 1) ? g_k : g_v;
#pragma unroll
    for (int i = 0; i < 4; i++) {
        float4 r;
        r.x = acc[i][0]; r.y = acc[i][1]; r.z = acc[i][2]; r.w = acc[i][3];
        *(float4*)&outp[(size_t)(m0 + ty * 4 + i) * HS + tx * 4] = r;
    }
}

// ---------------------------------------------------------------------------
// Flash attention: per block 64 queries, stream 64-key tiles, online softmax.
// Smem layout (dynamic, ~65 KB):
//   Qts[d][row]  (dim-major, pre-scaled)    4096 floats
//   Kts[d][key]  (dim-major)                4096 floats
//   Vs [key][d]                             4096 floats
//   Ps [row][key] stride 68 (pad vs banks)  4352 floats
//   Madd[64]
// ---------------------------------------------------------------------------
#define PS_STRIDE 68
#define ATTN_SMEM_FLOATS (4096 * 3 + 64 * PS_STRIDE + 64)

__global__ void __launch_bounds__(256) attn_kernel(float* __restrict__ out) {
    extern __shared__ float sm[];
    float (*Qts)[64]        = (float(*)[64])sm;
    float (*Kts)[64]        = (float(*)[64])(sm + 4096);
    float (*Vs)[64]         = (float(*)[64])(sm + 8192);
    float (*Ps)[PS_STRIDE]  = (float(*)[PS_STRIDE])(sm + 12288);
    float* Madd             = sm + 12288 + 64 * PS_STRIDE;

    const int tid = threadIdx.x;
    const int tx = tid & 15, ty = tid >> 4;
    const int b  = blockIdx.y;
    const int q0 = blockIdx.x << 6;

    const float* qb = g_q + ((size_t)b * SEQ + q0) * HS;
    const float* kb = g_k + (size_t)b * SEQ * HS;
    const float* vb = g_v + (size_t)b * SEQ * HS;
    const float* mb = g_maskadd + (size_t)b * SEQ;

    // Load Q tile transposed (dim-major), pre-scaled by 1/sqrt(hs)
    {
        int r  = tid >> 2;
        int d0 = (tid & 3) << 4;
#pragma unroll
        for (int i = 0; i < 4; i++) {
            float4 v4 = *(const float4*)&qb[(size_t)r * HS + d0 + i * 4];
            Qts[d0 + i * 4 + 0][r] = v4.x * SCALE;
            Qts[d0 + i * 4 + 1][r] = v4.y * SCALE;
            Qts[d0 + i * 4 + 2][r] = v4.z * SCALE;
            Qts[d0 + i * 4 + 3][r] = v4.w * SCALE;
        }
    }

    float o[4][4] = {};
    float m_i[4], l_i[4];
#pragma unroll
    for (int i = 0; i < 4; i++) { m_i[i] = -1e38f; l_i[i] = 0.0f; }

    for (int k0 = 0; k0 < SEQ; k0 += 64) {
        __syncthreads();  // previous PV reads done before overwriting tiles
        {
            int r  = tid >> 2;
            int d0 = (tid & 3) << 4;
#pragma unroll
            for (int i = 0; i < 4; i++) {
                float4 kv = *(const float4*)&kb[(size_t)(k0 + r) * HS + d0 + i * 4];
                Kts[d0 + i * 4 + 0][r] = kv.x;
                Kts[d0 + i * 4 + 1][r] = kv.y;
                Kts[d0 + i * 4 + 2][r] = kv.z;
                Kts[d0 + i * 4 + 3][r] = kv.w;
                *(float4*)&Vs[r][d0 + i * 4] =
                    *(const float4*)&vb[(size_t)(k0 + r) * HS + d0 + i * 4];
            }
            if (tid < 64) Madd[tid] = mb[k0 + tid];
        }
        __syncthreads();

        // S = Q @ K^T  (4x4 per thread)
        float s[4][4] = {};
#pragma unroll 16
        for (int d = 0; d < 64; d++) {
            float4 a  = *(float4*)&Qts[d][ty << 2];
            float4 bq = *(float4*)&Kts[d][tx << 2];
            s[0][0] += a.x * bq.x; s[0][1] += a.x * bq.y; s[0][2] += a.x * bq.z; s[0][3] += a.x * bq.w;
            s[1][0] += a.y * bq.x; s[1][1] += a.y * bq.y; s[1][2] += a.y * bq.z; s[1][3] += a.y * bq.w;
            s[2][0] += a.z * bq.x; s[2][1] += a.z * bq.y; s[2][2] += a.z * bq.z; s[2][3] += a.z * bq.w;
            s[3][0] += a.w * bq.x; s[3][1] += a.w * bq.y; s[3][2] += a.w * bq.z; s[3][3] += a.w * bq.w;
        }

        float madd[4];
#pragma unroll
        for (int j = 0; j < 4; j++) madd[j] = Madd[(tx << 2) + j];

#pragma unroll
        for (int i = 0; i < 4; i++) {
            s[i][0] += madd[0]; s[i][1] += madd[1];
            s[i][2] += madd[2]; s[i][3] += madd[3];
            float mx = fmaxf(fmaxf(s[i][0], s[i][1]), fmaxf(s[i][2], s[i][3]));
#pragma unroll
            for (int off = 8; off; off >>= 1)
                mx = fmaxf(mx, __shfl_xor_sync(0xffffffffu, mx, off, 16));
            float mnew = fmaxf(m_i[i], mx);
            float corr = __expf(m_i[i] - mnew);
            float p0 = __expf(s[i][0] - mnew);
            float p1 = __expf(s[i][1] - mnew);
            float p2 = __expf(s[i][2] - mnew);
            float p3 = __expf(s[i][3] - mnew);
            float4 pv; pv.x = p0; pv.y = p1; pv.z = p2; pv.w = p3;
            *(float4*)&Ps[(ty << 2) + i][tx << 2] = pv;
            float rs = (p0 + p1) + (p2 + p3);
#pragma unroll
            for (int off = 8; off; off >>= 1)
                rs += __shfl_xor_sync(0xffffffffu, rs, off, 16);
            l_i[i] = l_i[i] * corr + rs;
            m_i[i] = mnew;
            o[i][0] *= corr; o[i][1] *= corr; o[i][2] *= corr; o[i][3] *= corr;
        }
        __syncthreads();

        // O += P @ V
#pragma unroll 16
        for (int kk = 0; kk < 64; kk++) {
            float4 vv = *(float4*)&Vs[kk][tx << 2];
            float p0 = Ps[(ty << 2) + 0][kk];
            float p1 = Ps[(ty << 2) + 1][kk];
            float p2 = Ps[(ty << 2) + 2][kk];
            float p3 = Ps[(ty << 2) + 3][kk];
            o[0][0] += p0 * vv.x; o[0][1] += p0 * vv.y; o[0][2] += p0 * vv.z; o[0][3] += p0 * vv.w;
            o[1][0] += p1 * vv.x; o[1][1] += p1 * vv.y; o[1][2] += p1 * vv.z; o[1][3] += p1 * vv.w;
            o[2][0] += p2 * vv.x; o[2][1] += p2 * vv.y; o[2][2] += p2 * vv.z; o[2][3] += p2 * vv.w;
            o[3][0] += p3 * vv.x; o[3][1] += p3 * vv.y; o[3][2] += p3 * vv.z; o[3][3] += p3 * vv.w;
        }
    }

    // Epilogue: normalize by l and store
#pragma unroll
    for (int i = 0; i < 4; i++) {
        float inv = 1.0f / l_i[i];
        float4 r;
        r.x = o[i][0] * inv; r.y = o[i][1] * inv;
        r.z = o[i][2] * inv; r.w = o[i][3] * inv;
        *(float4*)&out[((size_t)b * SEQ + q0 + (ty << 2) + i) * HS + (tx << 2)] = r;
    }
}

extern "C" void kernel_launch(void* const* d_in, const int* in_sizes, int n_in,
                              void* d_out, int out_size) {
    const float*         x    = (const float*)d_in[0];
    const unsigned char* mask = (const unsigned char*)d_in[1];
    const float*         W    = (const float*)d_in[2];
    float*               out  = (float*)d_out;
    (void)in_sizes; (void)n_in; (void)out_size;

    mask_kernel<<<(BATCH * SEQ) / 256, 256>>>(mask);
    qkv_kernel<<<dim3(3, (BATCH * SEQ) / 64), 256>>>(x, W);

    const int attn_smem = ATTN_SMEM_FLOATS * (int)sizeof(float);
    cudaFuncSetAttribute(attn_kernel, cudaFuncAttributeMaxDynamicSharedMemorySize, attn_smem);
    attn_kernel<<<dim3(SEQ / 64, BATCH), 256, attn_smem>>>(out);
}

// round 9
// speedup vs baseline: 2.3436x; 2.2116x over previous
#include <cuda_runtime.h>
#include <cuda_bf16.h>
#include <cstdint>

#define BATCH 4
#define SEQ   4096
#define DIM   1024
#define HS    64
#define NQKV  192
#define OFFS  14.0f

__device__ float         g_q[BATCH*SEQ*HS];        // pre-scaled by 1/8
__device__ __nv_bfloat16 g_k_hi[BATCH*SEQ*HS];
__device__ __nv_bfloat16 g_k_lo[BATCH*SEQ*HS];
__device__ __nv_bfloat16 g_v_hi[BATCH*SEQ*HS];
__device__ __nv_bfloat16 g_v_lo[BATCH*SEQ*HS];
__device__ float         g_maskadd[BATCH*SEQ];

// ---------------- helpers ----------------
__device__ __forceinline__ uint32_t smem_u32(const void* p){
    uint32_t a;
    asm("{ .reg .u64 t; cvta.to.shared.u64 t, %1; cvt.u32.u64 %0, t; }" : "=r"(a) : "l"(p));
    return a;
}
#define CP16(d,s)   asm volatile("cp.async.cg.shared.global [%0], [%1], 16;" :: "r"((uint32_t)(d)), "l"(s) : "memory")
#define CP_COMMIT() asm volatile("cp.async.commit_group;" ::: "memory")
#define CP_WAIT0()  asm volatile("cp.async.wait_group 0;" ::: "memory")
#define CP_WAIT1()  asm volatile("cp.async.wait_group 1;" ::: "memory")

#define LDSM4(r, a) \
    asm volatile("ldmatrix.sync.aligned.m8n8.x4.shared.b16 {%0,%1,%2,%3}, [%4];" \
        : "=r"((r)[0]),"=r"((r)[1]),"=r"((r)[2]),"=r"((r)[3]) : "r"(a))
#define LDSM4T(r, a) \
    asm volatile("ldmatrix.sync.aligned.m8n8.x4.trans.shared.b16 {%0,%1,%2,%3}, [%4];" \
        : "=r"((r)[0]),"=r"((r)[1]),"=r"((r)[2]),"=r"((r)[3]) : "r"(a))

__device__ __forceinline__ void mma_bf16(float* d, const uint32_t* a, uint32_t b0, uint32_t b1){
    asm volatile("mma.sync.aligned.m16n8k16.row.col.f32.bf16.bf16.f32 "
        "{%0,%1,%2,%3}, {%4,%5,%6,%7}, {%8,%9}, {%0,%1,%2,%3};"
        : "+f"(d[0]),"+f"(d[1]),"+f"(d[2]),"+f"(d[3])
        : "r"(a[0]),"r"(a[1]),"r"(a[2]),"r"(a[3]), "r"(b0),"r"(b1));
}
__device__ __forceinline__ uint32_t pack2(__nv_bfloat16 a, __nv_bfloat16 b){
    uint16_t ua = *(uint16_t*)&a, ub = *(uint16_t*)&b;
    return (uint32_t)ua | ((uint32_t)ub << 16);
}
__device__ __forceinline__ void split_bf16(float f, __nv_bfloat16& h, __nv_bfloat16& l){
    h = __float2bfloat16(f);
    l = __float2bfloat16(f - __bfloat162float(h));
}

// ldmatrix address for tile at (row0, chunk-pair cp) in a [rows][64 bf16] swizzled
// layout (128B rows, 16B chunk index XOR row&7). Same mapping serves A, B(K), B(V-trans).
__device__ __forceinline__ uint32_t xaddr(uint32_t base, int row0, int cp, int lane){
    int sub = lane >> 3;
    int rr = row0 + (lane & 7) + ((sub & 1) << 3);
    int ch = cp * 2 + (sub >> 1);
    return base + rr * 128 + ((ch ^ (rr & 7)) << 4);
}

// ---------------- mask ----------------
__global__ void __launch_bounds__(256) mask_kernel(const unsigned char* __restrict__ raw){
    __shared__ int not_word;
    const int tid = threadIdx.x;
    if (tid == 0) not_word = 0;
    __syncthreads();
    if (tid < 64){
        unsigned int w = ((const unsigned int*)raw)[tid];
        if (w != 0u && w != 1u && w != 0x3f800000u) atomicOr(&not_word, 1);
    }
    __syncthreads();
    const int i = blockIdx.x * 256 + tid;
    bool on = (!not_word) ? (((const unsigned int*)raw)[i] != 0u) : (raw[i] != 0);
    g_maskadd[i] = on ? 0.0f : -1e30f;
}

// ---------------- QKV (fp32 FFMA, split-bf16 epilogue) ----------------
__global__ void __launch_bounds__(256) qkv_kernel(const float* __restrict__ x,
                                                  const float* __restrict__ W){
    __shared__ float As[64][32];
    __shared__ float Bs[32][64];
    const int tid = threadIdx.x, tx = tid & 15, ty = tid >> 4;
    const int m0 = blockIdx.y << 6, sect = blockIdx.x, n0 = sect * 64;
    float acc[4][4] = {};
    for (int kt = 0; kt < DIM; kt += 32){
#pragma unroll
        for (int i = 0; i < 2; i++){
            int idx = tid + i * 256, r = idx >> 3, c4 = idx & 7;
            *(float4*)&As[r][c4*4] = *(const float4*)&x[(size_t)(m0+r)*DIM + kt + c4*4];
        }
#pragma unroll
        for (int i = 0; i < 2; i++){
            int idx = tid + i * 256, r = idx >> 4, c4 = idx & 15;
            *(float4*)&Bs[r][c4*4] = *(const float4*)&W[(size_t)(kt+r)*NQKV + n0 + c4*4];
        }
        __syncthreads();
#pragma unroll
        for (int kk = 0; kk < 32; kk++){
            float a0 = As[ty*4+0][kk], a1 = As[ty*4+1][kk], a2 = As[ty*4+2][kk], a3 = As[ty*4+3][kk];
            float4 b = *(float4*)&Bs[kk][tx*4];
            acc[0][0]+=a0*b.x; acc[0][1]+=a0*b.y; acc[0][2]+=a0*b.z; acc[0][3]+=a0*b.w;
            acc[1][0]+=a1*b.x; acc[1][1]+=a1*b.y; acc[1][2]+=a1*b.z; acc[1][3]+=a1*b.w;
            acc[2][0]+=a2*b.x; acc[2][1]+=a2*b.y; acc[2][2]+=a2*b.z; acc[2][3]+=a2*b.w;
            acc[3][0]+=a3*b.x; acc[3][1]+=a3*b.y; acc[3][2]+=a3*b.z; acc[3][3]+=a3*b.w;
        }
        __syncthreads();
    }
#pragma unroll
    for (int i = 0; i < 4; i++){
        int grow = m0 + ty*4 + i;
        if (sect == 0){
            float4 r; r.x=acc[i][0]*0.125f; r.y=acc[i][1]*0.125f; r.z=acc[i][2]*0.125f; r.w=acc[i][3]*0.125f;
            *(float4*)&g_q[(size_t)grow*HS + tx*4] = r;
        } else {
            __nv_bfloat16 h0,l0,h1,l1,h2,l2,h3,l3;
            split_bf16(acc[i][0],h0,l0); split_bf16(acc[i][1],h1,l1);
            split_bf16(acc[i][2],h2,l2); split_bf16(acc[i][3],h3,l3);
            uint2 vh; vh.x = pack2(h0,h1); vh.y = pack2(h2,h3);
            uint2 vl; vl.x = pack2(l0,l1); vl.y = pack2(l2,l3);
            if (sect == 1){
                *(uint2*)&g_k_hi[(size_t)grow*HS + tx*4] = vh;
                *(uint2*)&g_k_lo[(size_t)grow*HS + tx*4] = vl;
            } else {
                *(uint2*)&g_v_hi[(size_t)grow*HS + tx*4] = vh;
                *(uint2*)&g_v_lo[(size_t)grow*HS + tx*4] = vl;
            }
        }
    }
}

// ---------------- attention (mma.sync bf16, split hi/lo) ----------------
#define SM_QH   0
#define SM_QL   16384
#define SM_BUF  32768
#define BUFSZ   65536
#define OF_KH   0
#define OF_KL   16384
#define OF_VH   32768
#define OF_VL   49152
#define SM_MASK 163840
#define ATTN_SMEM 164864

__device__ __forceinline__ void stage(uint32_t sb, int b, int k0, int t, int tid){
    uint32_t buf = sb + SM_BUF + (t & 1) * BUFSZ;
    const char* kh = (const char*)(g_k_hi + ((size_t)b*SEQ + k0)*HS);
    const char* kl = (const char*)(g_k_lo + ((size_t)b*SEQ + k0)*HS);
    const char* vh = (const char*)(g_v_hi + ((size_t)b*SEQ + k0)*HS);
    const char* vl = (const char*)(g_v_lo + ((size_t)b*SEQ + k0)*HS);
#pragma unroll
    for (int it = 0; it < 4; it++){
        int i = tid + it*256, row = i >> 3, c = i & 7;
        uint32_t dst = (uint32_t)row*128 + ((uint32_t)(c ^ (row & 7)) << 4);
        size_t   src = (size_t)row*128 + c*16;
        CP16(buf + OF_KH + dst, kh + src);
        CP16(buf + OF_KL + dst, kl + src);
        CP16(buf + OF_VH + dst, vh + src);
        CP16(buf + OF_VL + dst, vl + src);
    }
    if (tid < 32)
        CP16(sb + SM_MASK + (t & 1)*512 + tid*16, g_maskadd + (size_t)b*SEQ + k0 + tid*4);
}

__global__ void __launch_bounds__(256) attn_kernel(float* __restrict__ out){
    extern __shared__ char sm[];
    uint32_t sb = smem_u32(sm);
    const int tid = threadIdx.x, w = tid >> 5, lane = tid & 31;
    const int g = lane >> 2, tig = lane & 3;
    const int b = blockIdx.y, q0 = blockIdx.x << 7;

    stage(sb, b, 0, 0, tid);   CP_COMMIT();
    stage(sb, b, 128, 1, tid); CP_COMMIT();

    // Q (fp32, pre-scaled) -> split bf16 hi/lo into swizzled smem
#pragma unroll
    for (int it = 0; it < 4; it++){
        int ch = tid + it*256;
        int row = ch >> 3, c = ch & 7;
        const float4* qp = (const float4*)(g_q + ((size_t)b*SEQ + q0 + row)*HS + c*8);
        float4 v0 = qp[0], v1 = qp[1];
        __nv_bfloat16 h0,l0,h1,l1,h2,l2,h3,l3,h4,l4,h5,l5,h6,l6,h7,l7;
        split_bf16(v0.x,h0,l0); split_bf16(v0.y,h1,l1); split_bf16(v0.z,h2,l2); split_bf16(v0.w,h3,l3);
        split_bf16(v1.x,h4,l4); split_bf16(v1.y,h5,l5); split_bf16(v1.z,h6,l6); split_bf16(v1.w,h7,l7);
        uint4 hh; hh.x = pack2(h0,h1); hh.y = pack2(h2,h3); hh.z = pack2(h4,h5); hh.w = pack2(h6,h7);
        uint4 ll; ll.x = pack2(l0,l1); ll.y = pack2(l2,l3); ll.z = pack2(l4,l5); ll.w = pack2(l6,l7);
        uint32_t d = (uint32_t)row*128 + ((uint32_t)(c ^ (row & 7)) << 4);
        *(uint4*)(sm + SM_QH + d) = hh;
        *(uint4*)(sm + SM_QL + d) = ll;
    }
    __syncthreads();

    uint32_t qh[4][4], ql[4][4];
#pragma unroll
    for (int ks = 0; ks < 4; ks++){
        LDSM4(qh[ks], xaddr(sb + SM_QH, w*16, ks, lane));
        LDSM4(ql[ks], xaddr(sb + SM_QL, w*16, ks, lane));
    }

    float o[8][4];
#pragma unroll
    for (int j = 0; j < 8; j++){ o[j][0]=0.f; o[j][1]=0.f; o[j][2]=0.f; o[j][3]=0.f; }
    float lp0 = 0.f, lp1 = 0.f;

    for (int t = 0; t < 32; t++){
        if (t < 31) { CP_WAIT1(); } else { CP_WAIT0(); }
        __syncthreads();
        const uint32_t buf = sb + SM_BUF + (t & 1)*BUFSZ;
        const char* msk = sm + SM_MASK + (t & 1)*512;
#pragma unroll
        for (int h2 = 0; h2 < 2; h2++){
            const int kb = h2 * 64;
            float s[8][4];
#pragma unroll
            for (int j = 0; j < 8; j++){ s[j][0]=0.f; s[j][1]=0.f; s[j][2]=0.f; s[j][3]=0.f; }
#pragma unroll
            for (int ks = 0; ks < 4; ks++){
#pragma unroll
                for (int p = 0; p < 4; p++){
                    uint32_t kh4[4], kl4[4];
                    LDSM4(kh4, xaddr(buf + OF_KH, kb + p*16, ks, lane));
                    LDSM4(kl4, xaddr(buf + OF_KL, kb + p*16, ks, lane));
                    mma_bf16(s[p*2],   qh[ks], kh4[0], kh4[2]);
                    mma_bf16(s[p*2],   ql[ks], kh4[0], kh4[2]);
                    mma_bf16(s[p*2],   qh[ks], kl4[0], kl4[2]);
                    mma_bf16(s[p*2+1], qh[ks], kh4[1], kh4[3]);
                    mma_bf16(s[p*2+1], ql[ks], kh4[1], kh4[3]);
                    mma_bf16(s[p*2+1], qh[ks], kl4[1], kl4[3]);
                }
            }
            uint32_t ph[4][4], pl[4][4];
#pragma unroll
            for (int j = 0; j < 8; j++){
                float2 mv = *(const float2*)(msk + (kb + j*8 + 2*tig)*4);
                float p0 = __expf(s[j][0] + mv.x - OFFS);
                float p1 = __expf(s[j][1] + mv.y - OFFS);
                float p2 = __expf(s[j][2] + mv.x - OFFS);
                float p3 = __expf(s[j][3] + mv.y - OFFS);
                lp0 += p0 + p1; lp1 += p2 + p3;
                __nv_bfloat16 a0,b0,a1,b1,a2,b2,a3,b3;
                split_bf16(p0,a0,b0); split_bf16(p1,a1,b1);
                split_bf16(p2,a2,b2); split_bf16(p3,a3,b3);
                int kk = j >> 1, od = (j & 1) << 1;
                ph[kk][od] = pack2(a0,a1); ph[kk][od+1] = pack2(a2,a3);
                pl[kk][od] = pack2(b0,b1); pl[kk][od+1] = pack2(b2,b3);
            }
#pragma unroll
            for (int kk = 0; kk < 4; kk++){
#pragma unroll
                for (int dp = 0; dp < 4; dp++){
                    uint32_t vh4[4], vl4[4];
                    LDSM4T(vh4, xaddr(buf + OF_VH, kb + kk*16, dp, lane));
                    LDSM4T(vl4, xaddr(buf + OF_VL, kb + kk*16, dp, lane));
                    mma_bf16(o[dp*2],   ph[kk], vh4[0], vh4[1]);
                    mma_bf16(o[dp*2],   pl[kk], vh4[0], vh4[1]);
                    mma_bf16(o[dp*2],   ph[kk], vl4[0], vl4[1]);
                    mma_bf16(o[dp*2+1], ph[kk], vh4[2], vh4[3]);
                    mma_bf16(o[dp*2+1], pl[kk], vh4[2], vh4[3]);
                    mma_bf16(o[dp*2+1], ph[kk], vl4[2], vl4[3]);
                }
            }
        }
        __syncthreads();
        if (t + 2 < 32){ stage(sb, b, (t+2)*128, t+2, tid); CP_COMMIT(); }
    }

    lp0 += __shfl_xor_sync(0xffffffffu, lp0, 1);
    lp0 += __shfl_xor_sync(0xffffffffu, lp0, 2);
    lp1 += __shfl_xor_sync(0xffffffffu, lp1, 1);
    lp1 += __shfl_xor_sync(0xffffffffu, lp1, 2);
    float i0 = 1.0f / lp0, i1 = 1.0f / lp1;

    float* o0 = out + ((size_t)b*SEQ + q0 + w*16 + g)*HS;
    float* o1 = o0 + 8*HS;
#pragma unroll
    for (int j = 0; j < 8; j++){
        float2 v0; v0.x = o[j][0]*i0; v0.y = o[j][1]*i0;
        float2 v1; v1.x = o[j][2]*i1; v1.y = o[j][3]*i1;
        *(float2*)(o0 + j*8 + 2*tig) = v0;
        *(float2*)(o1 + j*8 + 2*tig) = v1;
    }
}

extern "C" void kernel_launch(void* const* d_in, const int* in_sizes, int n_in,
                              void* d_out, int out_size){
    const float*         x    = (const float*)d_in[0];
    const unsigned char* mask = (const unsigned char*)d_in[1];
    const float*         W    = (const float*)d_in[2];
    float*               out  = (float*)d_out;
    (void)in_sizes; (void)n_in; (void)out_size;

    mask_kernel<<<(BATCH*SEQ)/256, 256>>>(mask);
    qkv_kernel<<<dim3(3, (BATCH*SEQ)/64), 256>>>(x, W);
    cudaFuncSetAttribute(attn_kernel, cudaFuncAttributeMaxDynamicSharedMemorySize, ATTN_SMEM);
    attn_kernel<<<dim3(SEQ/128, BATCH), 256, ATTN_SMEM>>>(out);
}

// round 10
// speedup vs baseline: 3.3561x; 1.4321x over previous
#include <cuda_runtime.h>
#include <cuda_bf16.h>
#include <cstdint>

#define BATCH 4
#define SEQ   4096
#define DIM   1024
#define HS    64
#define NQKV  192
#define OFFS  14.0f

__device__ __align__(256) float         g_q[BATCH*SEQ*HS];        // pre-scaled by 1/8
__device__ __align__(256) __nv_bfloat16 g_k_hi[BATCH*SEQ*HS];
__device__ __align__(256) __nv_bfloat16 g_k_lo[BATCH*SEQ*HS];
__device__ __align__(256) __nv_bfloat16 g_v_hi[BATCH*SEQ*HS];
__device__ __align__(256) __nv_bfloat16 g_v_lo[BATCH*SEQ*HS];
__device__ __align__(256) __nv_bfloat16 g_x_hi[BATCH*SEQ*DIM];
__device__ __align__(256) __nv_bfloat16 g_x_lo[BATCH*SEQ*DIM];
__device__ __align__(256) __nv_bfloat16 g_w_hi[DIM*NQKV];
__device__ __align__(256) __nv_bfloat16 g_w_lo[DIM*NQKV];
__device__ __align__(256) float         g_maskadd[BATCH*SEQ];

// ---------------- helpers ----------------
__device__ __forceinline__ uint32_t smem_u32(const void* p){
    uint32_t a;
    asm("{ .reg .u64 t; cvta.to.shared.u64 t, %1; cvt.u32.u64 %0, t; }" : "=r"(a) : "l"(p));
    return a;
}
#define CP16(d,s)   asm volatile("cp.async.cg.shared.global [%0], [%1], 16;" :: "r"((uint32_t)(d)), "l"(s) : "memory")
#define CP_COMMIT() asm volatile("cp.async.commit_group;" ::: "memory")
#define CP_WAIT0()  asm volatile("cp.async.wait_group 0;" ::: "memory")
#define CP_WAIT1()  asm volatile("cp.async.wait_group 1;" ::: "memory")

#define LDSM4(r, a) \
    asm volatile("ldmatrix.sync.aligned.m8n8.x4.shared.b16 {%0,%1,%2,%3}, [%4];" \
        : "=r"((r)[0]),"=r"((r)[1]),"=r"((r)[2]),"=r"((r)[3]) : "r"(a))
#define LDSM4T(r, a) \
    asm volatile("ldmatrix.sync.aligned.m8n8.x4.trans.shared.b16 {%0,%1,%2,%3}, [%4];" \
        : "=r"((r)[0]),"=r"((r)[1]),"=r"((r)[2]),"=r"((r)[3]) : "r"(a))

__device__ __forceinline__ void mma_bf16(float* d, const uint32_t* a, uint32_t b0, uint32_t b1){
    asm volatile("mma.sync.aligned.m16n8k16.row.col.f32.bf16.bf16.f32 "
        "{%0,%1,%2,%3}, {%4,%5,%6,%7}, {%8,%9}, {%0,%1,%2,%3};"
        : "+f"(d[0]),"+f"(d[1]),"+f"(d[2]),"+f"(d[3])
        : "r"(a[0]),"r"(a[1]),"r"(a[2]),"r"(a[3]), "r"(b0),"r"(b1));
}
__device__ __forceinline__ uint32_t pack2(__nv_bfloat16 a, __nv_bfloat16 b){
    uint16_t ua = *(uint16_t*)&a, ub = *(uint16_t*)&b;
    return (uint32_t)ua | ((uint32_t)ub << 16);
}
__device__ __forceinline__ void split_bf16(float f, __nv_bfloat16& h, __nv_bfloat16& l){
    h = __float2bfloat16(f);
    l = __float2bfloat16(f - __bfloat162float(h));
}
// ldmatrix address for tile at (row0, 16B-chunk-pair cp) in [rows][64 bf16]
// swizzled layout (128B rows, chunk index XOR (row&7)).
__device__ __forceinline__ uint32_t xaddr(uint32_t base, int row0, int cp, int lane){
    int sub = lane >> 3;
    int rr = row0 + (lane & 7) + ((sub & 1) << 3);
    int ch = cp * 2 + (sub >> 1);
    return base + rr * 128 + ((ch ^ (rr & 7)) << 4);
}

// ---------------- mask ----------------
__global__ void __launch_bounds__(256) mask_kernel(const unsigned char* __restrict__ raw){
    __shared__ int not_word;
    const int tid = threadIdx.x;
    if (tid == 0) not_word = 0;
    __syncthreads();
    if (tid < 64){
        unsigned int w = ((const unsigned int*)raw)[tid];
        if (w != 0u && w != 1u && w != 0x3f800000u) atomicOr(&not_word, 1);
    }
    __syncthreads();
    const int i = blockIdx.x * 256 + tid;
    bool on = (!not_word) ? (((const unsigned int*)raw)[i] != 0u) : (raw[i] != 0);
    g_maskadd[i] = on ? 0.0f : -1e30f;
}

// ---------------- input conversions (split fp32 -> bf16 hi/lo) ----------------
__global__ void __launch_bounds__(256) xconv_kernel(const float* __restrict__ x){
    size_t i = (size_t)blockIdx.x * 256 + threadIdx.x;   // float4 index
    float4 v = ((const float4*)x)[i];
    __nv_bfloat16 h0,l0,h1,l1,h2,l2,h3,l3;
    split_bf16(v.x,h0,l0); split_bf16(v.y,h1,l1);
    split_bf16(v.z,h2,l2); split_bf16(v.w,h3,l3);
    uint2 hh; hh.x = pack2(h0,h1); hh.y = pack2(h2,h3);
    uint2 ll; ll.x = pack2(l0,l1); ll.y = pack2(l2,l3);
    *(uint2*)&g_x_hi[i*4] = hh;
    *(uint2*)&g_x_lo[i*4] = ll;
}
__global__ void __launch_bounds__(256) wconv_kernel(const float* __restrict__ W){
    size_t i = (size_t)blockIdx.x * 256 + threadIdx.x;
    float4 v = ((const float4*)W)[i];
    __nv_bfloat16 h0,l0,h1,l1,h2,l2,h3,l3;
    split_bf16(v.x,h0,l0); split_bf16(v.y,h1,l1);
    split_bf16(v.z,h2,l2); split_bf16(v.w,h3,l3);
    uint2 hh; hh.x = pack2(h0,h1); hh.y = pack2(h2,h3);
    uint2 ll; ll.x = pack2(l0,l1); ll.y = pack2(l2,l3);
    *(uint2*)&g_w_hi[i*4] = hh;
    *(uint2*)&g_w_lo[i*4] = ll;
}

// ---------------- QKV GEMM (mma.sync bf16 split) ----------------
// C[16384x192] = x @ W.  Grid (3 sections, 128 row-blocks). CTA: 128 rows x 64 cols.
// 8 warps x 16 rows each; per-warp 8 n8-tiles of accumulators.
#define QK_XH  0
#define QK_XL  16384
#define QK_WH  32768
#define QK_WL  40960
#define QK_BUF 49152
#define QKV_SMEM (2*QK_BUF)

__device__ __forceinline__ void qkv_stage(uint32_t sb, int sect, int m0, int kt, int tid){
    uint32_t buf = sb + (kt & 1) * QK_BUF;
    const int k0 = kt * 64;
#pragma unroll
    for (int it = 0; it < 4; it++){
        int i = tid + it*256, row = i >> 3, c = i & 7;
        uint32_t dst = (uint32_t)row*128 + ((uint32_t)(c ^ (row & 7)) << 4);
        size_t   src = (size_t)(m0 + row)*DIM + k0 + c*8;
        CP16(buf + QK_XH + dst, (const char*)g_x_hi + src*2);
        CP16(buf + QK_XL + dst, (const char*)g_x_lo + src*2);
    }
#pragma unroll
    for (int it = 0; it < 2; it++){
        int i = tid + it*256, row = i >> 3, c = i & 7;
        uint32_t dst = (uint32_t)row*128 + ((uint32_t)(c ^ (row & 7)) << 4);
        size_t   src = (size_t)(k0 + row)*NQKV + sect*64 + c*8;
        CP16(buf + QK_WH + dst, (const char*)g_w_hi + src*2);
        CP16(buf + QK_WL + dst, (const char*)g_w_lo + src*2);
    }
}

__global__ void __launch_bounds__(256) qkv_mma_kernel(){
    extern __shared__ char sm[];
    uint32_t sb = smem_u32(sm);
    const int tid = threadIdx.x, w = tid >> 5, lane = tid & 31;
    const int g = lane >> 2, tig = lane & 3;
    const int sect = blockIdx.x, m0 = blockIdx.y << 7;

    qkv_stage(sb, sect, m0, 0, tid); CP_COMMIT();
    qkv_stage(sb, sect, m0, 1, tid); CP_COMMIT();

    float acc[8][4];
#pragma unroll
    for (int j = 0; j < 8; j++){ acc[j][0]=0.f; acc[j][1]=0.f; acc[j][2]=0.f; acc[j][3]=0.f; }

    for (int kt = 0; kt < 16; kt++){
        if (kt < 15) { CP_WAIT1(); } else { CP_WAIT0(); }
        __syncthreads();
        const uint32_t buf = sb + (kt & 1) * QK_BUF;
#pragma unroll
        for (int ks = 0; ks < 4; ks++){
            uint32_t ah[4], al[4];
            LDSM4(ah, xaddr(buf + QK_XH, w*16, ks, lane));
            LDSM4(al, xaddr(buf + QK_XL, w*16, ks, lane));
#pragma unroll
            for (int np = 0; np < 4; np++){
                uint32_t bh[4], bl[4];
                LDSM4T(bh, xaddr(buf + QK_WH, ks*16, np, lane));
                LDSM4T(bl, xaddr(buf + QK_WL, ks*16, np, lane));
                mma_bf16(acc[np*2],   ah, bh[0], bh[1]);
                mma_bf16(acc[np*2],   al, bh[0], bh[1]);
                mma_bf16(acc[np*2],   ah, bl[0], bl[1]);
                mma_bf16(acc[np*2+1], ah, bh[2], bh[3]);
                mma_bf16(acc[np*2+1], al, bh[2], bh[3]);
                mma_bf16(acc[np*2+1], ah, bl[2], bl[3]);
            }
        }
        __syncthreads();
        if (kt + 2 < 16){ qkv_stage(sb, sect, m0, kt + 2, tid); CP_COMMIT(); }
    }

    const int r0 = m0 + w*16 + g;
#pragma unroll
    for (int j = 0; j < 8; j++){
        const int col = j*8 + tig*2;
        if (sect == 0){
            float2 v0; v0.x = acc[j][0]*0.125f; v0.y = acc[j][1]*0.125f;
            float2 v1; v1.x = acc[j][2]*0.125f; v1.y = acc[j][3]*0.125f;
            *(float2*)&g_q[(size_t)r0*HS + col]       = v0;
            *(float2*)&g_q[(size_t)(r0+8)*HS + col]   = v1;
        } else {
            __nv_bfloat16 h0,l0,h1,l1,h2,l2,h3,l3;
            split_bf16(acc[j][0],h0,l0); split_bf16(acc[j][1],h1,l1);
            split_bf16(acc[j][2],h2,l2); split_bf16(acc[j][3],h3,l3);
            __nv_bfloat16* dh = (sect == 1) ? g_k_hi : g_v_hi;
            __nv_bfloat16* dl = (sect == 1) ? g_k_lo : g_v_lo;
            *(uint32_t*)&dh[(size_t)r0*HS + col]     = pack2(h0,h1);
            *(uint32_t*)&dl[(size_t)r0*HS + col]     = pack2(l0,l1);
            *(uint32_t*)&dh[(size_t)(r0+8)*HS + col] = pack2(h2,h3);
            *(uint32_t*)&dl[(size_t)(r0+8)*HS + col] = pack2(l2,l3);
        }
    }
}

// ---------------- attention (mma.sync bf16, split hi/lo) ----------------
#define SM_QH   0
#define SM_QL   16384
#define SM_BUF  32768
#define BUFSZ   65536
#define OF_KH   0
#define OF_KL   16384
#define OF_VH   32768
#define OF_VL   49152
#define SM_MASK 163840
#define ATTN_SMEM 164864

__device__ __forceinline__ void stage(uint32_t sb, int b, int k0, int t, int tid){
    uint32_t buf = sb + SM_BUF + (t & 1) * BUFSZ;
    const char* kh = (const char*)(g_k_hi + ((size_t)b*SEQ + k0)*HS);
    const char* kl = (const char*)(g_k_lo + ((size_t)b*SEQ + k0)*HS);
    const char* vh = (const char*)(g_v_hi + ((size_t)b*SEQ + k0)*HS);
    const char* vl = (const char*)(g_v_lo + ((size_t)b*SEQ + k0)*HS);
#pragma unroll
    for (int it = 0; it < 4; it++){
        int i = tid + it*256, row = i >> 3, c = i & 7;
        uint32_t dst = (uint32_t)row*128 + ((uint32_t)(c ^ (row & 7)) << 4);
        size_t   src = (size_t)row*128 + c*16;
        CP16(buf + OF_KH + dst, kh + src);
        CP16(buf + OF_KL + dst, kl + src);
        CP16(buf + OF_VH + dst, vh + src);
        CP16(buf + OF_VL + dst, vl + src);
    }
    if (tid < 32)
        CP16(sb + SM_MASK + (t & 1)*512 + tid*16, g_maskadd + (size_t)b*SEQ + k0 + tid*4);
}

__global__ void __launch_bounds__(256) attn_kernel(float* __restrict__ out){
    extern __shared__ char sm[];
    uint32_t sb = smem_u32(sm);
    const int tid = threadIdx.x, w = tid >> 5, lane = tid & 31;
    const int g = lane >> 2, tig = lane & 3;
    const int b = blockIdx.y, q0 = blockIdx.x << 7;

    stage(sb, b, 0, 0, tid);   CP_COMMIT();
    stage(sb, b, 128, 1, tid); CP_COMMIT();

    // Q (fp32, pre-scaled) -> split bf16 hi/lo into swizzled smem
#pragma unroll
    for (int it = 0; it < 4; it++){
        int ch = tid + it*256;
        int row = ch >> 3, c = ch & 7;
        const float4* qp = (const float4*)(g_q + ((size_t)b*SEQ + q0 + row)*HS + c*8);
        float4 v0 = qp[0], v1 = qp[1];
        __nv_bfloat16 h0,l0,h1,l1,h2,l2,h3,l3,h4,l4,h5,l5,h6,l6,h7,l7;
        split_bf16(v0.x,h0,l0); split_bf16(v0.y,h1,l1); split_bf16(v0.z,h2,l2); split_bf16(v0.w,h3,l3);
        split_bf16(v1.x,h4,l4); split_bf16(v1.y,h5,l5); split_bf16(v1.z,h6,l6); split_bf16(v1.w,h7,l7);
        uint4 hh; hh.x = pack2(h0,h1); hh.y = pack2(h2,h3); hh.z = pack2(h4,h5); hh.w = pack2(h6,h7);
        uint4 ll; ll.x = pack2(l0,l1); ll.y = pack2(l2,l3); ll.z = pack2(l4,l5); ll.w = pack2(l6,l7);
        uint32_t d = (uint32_t)row*128 + ((uint32_t)(c ^ (row & 7)) << 4);
        *(uint4*)(sm + SM_QH + d) = hh;
        *(uint4*)(sm + SM_QL + d) = ll;
    }
    __syncthreads();

    uint32_t qh[4][4], ql[4][4];
#pragma unroll
    for (int ks = 0; ks < 4; ks++){
        LDSM4(qh[ks], xaddr(sb + SM_QH, w*16, ks, lane));
        LDSM4(ql[ks], xaddr(sb + SM_QL, w*16, ks, lane));
    }

    float o[8][4];
#pragma unroll
    for (int j = 0; j < 8; j++){ o[j][0]=0.f; o[j][1]=0.f; o[j][2]=0.f; o[j][3]=0.f; }
    float lp0 = 0.f, lp1 = 0.f;

    for (int t = 0; t < 32; t++){
        if (t < 31) { CP_WAIT1(); } else { CP_WAIT0(); }
        __syncthreads();
        const uint32_t buf = sb + SM_BUF + (t & 1)*BUFSZ;
        const char* msk = sm + SM_MASK + (t & 1)*512;
#pragma unroll
        for (int h2 = 0; h2 < 2; h2++){
            const int kb = h2 * 64;
            float s[8][4];
#pragma unroll
            for (int j = 0; j < 8; j++){ s[j][0]=0.f; s[j][1]=0.f; s[j][2]=0.f; s[j][3]=0.f; }
#pragma unroll
            for (int ks = 0; ks < 4; ks++){
#pragma unroll
                for (int p = 0; p < 4; p++){
                    uint32_t kh4[4], kl4[4];
                    LDSM4(kh4, xaddr(buf + OF_KH, kb + p*16, ks, lane));
                    LDSM4(kl4, xaddr(buf + OF_KL, kb + p*16, ks, lane));
                    mma_bf16(s[p*2],   qh[ks], kh4[0], kh4[2]);
                    mma_bf16(s[p*2],   ql[ks], kh4[0], kh4[2]);
                    mma_bf16(s[p*2],   qh[ks], kl4[0], kl4[2]);
                    mma_bf16(s[p*2+1], qh[ks], kh4[1], kh4[3]);
                    mma_bf16(s[p*2+1], ql[ks], kh4[1], kh4[3]);
                    mma_bf16(s[p*2+1], qh[ks], kl4[1], kl4[3]);
                }
            }
            uint32_t ph[4][4], pl[4][4];
#pragma unroll
            for (int j = 0; j < 8; j++){
                float2 mv = *(const float2*)(msk + (kb + j*8 + 2*tig)*4);
                float p0 = __expf(s[j][0] + mv.x - OFFS);
                float p1 = __expf(s[j][1] + mv.y - OFFS);
                float p2 = __expf(s[j][2] + mv.x - OFFS);
                float p3 = __expf(s[j][3] + mv.y - OFFS);
                lp0 += p0 + p1; lp1 += p2 + p3;
                __nv_bfloat16 a0,b0,a1,b1,a2,b2,a3,b3;
                split_bf16(p0,a0,b0); split_bf16(p1,a1,b1);
                split_bf16(p2,a2,b2); split_bf16(p3,a3,b3);
                int kk = j >> 1, od = (j & 1) << 1;
                ph[kk][od] = pack2(a0,a1); ph[kk][od+1] = pack2(a2,a3);
                pl[kk][od] = pack2(b0,b1); pl[kk][od+1] = pack2(b2,b3);
            }
#pragma unroll
            for (int kk = 0; kk < 4; kk++){
#pragma unroll
                for (int dp = 0; dp < 4; dp++){
                    uint32_t vh4[4], vl4[4];
                    LDSM4T(vh4, xaddr(buf + OF_VH, kb + kk*16, dp, lane));
                    LDSM4T(vl4, xaddr(buf + OF_VL, kb + kk*16, dp, lane));
                    mma_bf16(o[dp*2],   ph[kk], vh4[0], vh4[1]);
                    mma_bf16(o[dp*2],   pl[kk], vh4[0], vh4[1]);
                    mma_bf16(o[dp*2],   ph[kk], vl4[0], vl4[1]);
                    mma_bf16(o[dp*2+1], ph[kk], vh4[2], vh4[3]);
                    mma_bf16(o[dp*2+1], pl[kk], vh4[2], vh4[3]);
                    mma_bf16(o[dp*2+1], ph[kk], vl4[2], vl4[3]);
                }
            }
        }
        __syncthreads();
        if (t + 2 < 32){ stage(sb, b, (t+2)*128, t+2, tid); CP_COMMIT(); }
    }

    lp0 += __shfl_xor_sync(0xffffffffu, lp0, 1);
    lp0 += __shfl_xor_sync(0xffffffffu, lp0, 2);
    lp1 += __shfl_xor_sync(0xffffffffu, lp1, 1);
    lp1 += __shfl_xor_sync(0xffffffffu, lp1, 2);
    float i0 = 1.0f / lp0, i1 = 1.0f / lp1;

    float* o0 = out + ((size_t)b*SEQ + q0 + w*16 + g)*HS;
    float* o1 = o0 + 8*HS;
#pragma unroll
    for (int j = 0; j < 8; j++){
        float2 v0; v0.x = o[j][0]*i0; v0.y = o[j][1]*i0;
        float2 v1; v1.x = o[j][2]*i1; v1.y = o[j][3]*i1;
        *(float2*)(o0 + j*8 + 2*tig) = v0;
        *(float2*)(o1 + j*8 + 2*tig) = v1;
    }
}

extern "C" void kernel_launch(void* const* d_in, const int* in_sizes, int n_in,
                              void* d_out, int out_size){
    const float*         x    = (const float*)d_in[0];
    const unsigned char* mask = (const unsigned char*)d_in[1];
    const float*         W    = (const float*)d_in[2];
    float*               out  = (float*)d_out;
    (void)in_sizes; (void)n_in; (void)out_size;

    mask_kernel<<<(BATCH*SEQ)/256, 256>>>(mask);
    xconv_kernel<<<(BATCH*SEQ*DIM)/(256*4), 256>>>(x);
    wconv_kernel<<<(DIM*NQKV)/(256*4), 256>>>(W);
    cudaFuncSetAttribute(qkv_mma_kernel, cudaFuncAttributeMaxDynamicSharedMemorySize, QKV_SMEM);
    qkv_mma_kernel<<<dim3(3, (BATCH*SEQ)/128), 256, QKV_SMEM>>>();
    cudaFuncSetAttribute(attn_kernel, cudaFuncAttributeMaxDynamicSharedMemorySize, ATTN_SMEM);
    attn_kernel<<<dim3(SEQ/128, BATCH), 256, ATTN_SMEM>>>(out);
}

// round 11
// speedup vs baseline: 3.3836x; 1.0082x over previous
#include <cuda_runtime.h>
#include <cuda_bf16.h>
#include <cstdint>

#define BATCH 4
#define SEQ   4096
#define DIM   1024
#define HS    64
#define NQKV  192
#define OFFS  14.0f

__device__ __align__(256) float         g_q[BATCH*SEQ*HS];        // pre-scaled by 1/8
__device__ __align__(256) __nv_bfloat16 g_k_hi[BATCH*SEQ*HS];
__device__ __align__(256) __nv_bfloat16 g_k_lo[BATCH*SEQ*HS];
__device__ __align__(256) __nv_bfloat16 g_v_hi[BATCH*SEQ*HS];
__device__ __align__(256) __nv_bfloat16 g_v_lo[BATCH*SEQ*HS];
__device__ __align__(256) __nv_bfloat16 g_x_hi[BATCH*SEQ*DIM];
__device__ __align__(256) __nv_bfloat16 g_x_lo[BATCH*SEQ*DIM];
__device__ __align__(256) __nv_bfloat16 g_w_hi[DIM*NQKV];
__device__ __align__(256) __nv_bfloat16 g_w_lo[DIM*NQKV];
__device__ __align__(256) float         g_maskadd[BATCH*SEQ];

// ---------------- helpers ----------------
__device__ __forceinline__ uint32_t smem_u32(const void* p){
    uint32_t a;
    asm("{ .reg .u64 t; cvta.to.shared.u64 t, %1; cvt.u32.u64 %0, t; }" : "=r"(a) : "l"(p));
    return a;
}
#define CP16(d,s)   asm volatile("cp.async.cg.shared.global [%0], [%1], 16;" :: "r"((uint32_t)(d)), "l"(s) : "memory")
#define CP_COMMIT() asm volatile("cp.async.commit_group;" ::: "memory")
#define CP_WAIT0()  asm volatile("cp.async.wait_group 0;" ::: "memory")
#define CP_WAIT1()  asm volatile("cp.async.wait_group 1;" ::: "memory")

#define LDSM4(r, a) \
    asm volatile("ldmatrix.sync.aligned.m8n8.x4.shared.b16 {%0,%1,%2,%3}, [%4];" \
        : "=r"((r)[0]),"=r"((r)[1]),"=r"((r)[2]),"=r"((r)[3]) : "r"(a))
#define LDSM4T(r, a) \
    asm volatile("ldmatrix.sync.aligned.m8n8.x4.trans.shared.b16 {%0,%1,%2,%3}, [%4];" \
        : "=r"((r)[0]),"=r"((r)[1]),"=r"((r)[2]),"=r"((r)[3]) : "r"(a))

__device__ __forceinline__ void mma_bf16(float* d, const uint32_t* a, uint32_t b0, uint32_t b1){
    asm volatile("mma.sync.aligned.m16n8k16.row.col.f32.bf16.bf16.f32 "
        "{%0,%1,%2,%3}, {%4,%5,%6,%7}, {%8,%9}, {%0,%1,%2,%3};"
        : "+f"(d[0]),"+f"(d[1]),"+f"(d[2]),"+f"(d[3])
        : "r"(a[0]),"r"(a[1]),"r"(a[2]),"r"(a[3]), "r"(b0),"r"(b1));
}
__device__ __forceinline__ uint32_t pack2(__nv_bfloat16 a, __nv_bfloat16 b){
    uint16_t ua = *(uint16_t*)&a, ub = *(uint16_t*)&b;
    return (uint32_t)ua | ((uint32_t)ub << 16);
}
__device__ __forceinline__ void split_bf16(float f, __nv_bfloat16& h, __nv_bfloat16& l){
    h = __float2bfloat16(f);
    l = __float2bfloat16(f - __bfloat162float(h));
}
// ldmatrix address for tile at (row0, 16B-chunk-pair cp) in [rows][64 bf16]
// swizzled layout (128B rows, chunk index XOR (row&7)).
__device__ __forceinline__ uint32_t xaddr(uint32_t base, int row0, int cp, int lane){
    int sub = lane >> 3;
    int rr = row0 + (lane & 7) + ((sub & 1) << 3);
    int ch = cp * 2 + (sub >> 1);
    return base + rr * 128 + ((ch ^ (rr & 7)) << 4);
}

// ---------------- prep: mask (blocks 0..63) + W split (blocks 64..255) ----------------
__global__ void __launch_bounds__(256) prep_kernel(const unsigned char* __restrict__ raw,
                                                   const float* __restrict__ W){
    const int tid = threadIdx.x;
    if (blockIdx.x < 64){
        __shared__ int not_word;
        if (tid == 0) not_word = 0;
        __syncthreads();
        if (tid < 64){
            unsigned int w = ((const unsigned int*)raw)[tid];
            if (w != 0u && w != 1u && w != 0x3f800000u) atomicOr(&not_word, 1);
        }
        __syncthreads();
        const int i = blockIdx.x * 256 + tid;
        bool on = (!not_word) ? (((const unsigned int*)raw)[i] != 0u) : (raw[i] != 0);
        g_maskadd[i] = on ? 0.0f : -1e30f;
    } else {
        size_t i = (size_t)(blockIdx.x - 64) * 256 + tid;   // float4 index, 192 blocks
        float4 v = ((const float4*)W)[i];
        __nv_bfloat16 h0,l0,h1,l1,h2,l2,h3,l3;
        split_bf16(v.x,h0,l0); split_bf16(v.y,h1,l1);
        split_bf16(v.z,h2,l2); split_bf16(v.w,h3,l3);
        uint2 hh; hh.x = pack2(h0,h1); hh.y = pack2(h2,h3);
        uint2 ll; ll.x = pack2(l0,l1); ll.y = pack2(l2,l3);
        *(uint2*)&g_w_hi[i*4] = hh;
        *(uint2*)&g_w_lo[i*4] = ll;
    }
}

__global__ void __launch_bounds__(256) xconv_kernel(const float* __restrict__ x){
    size_t i = (size_t)blockIdx.x * 256 + threadIdx.x;   // float4 index
    float4 v = ((const float4*)x)[i];
    __nv_bfloat16 h0,l0,h1,l1,h2,l2,h3,l3;
    split_bf16(v.x,h0,l0); split_bf16(v.y,h1,l1);
    split_bf16(v.z,h2,l2); split_bf16(v.w,h3,l3);
    uint2 hh; hh.x = pack2(h0,h1); hh.y = pack2(h2,h3);
    uint2 ll; ll.x = pack2(l0,l1); ll.y = pack2(l2,l3);
    *(uint2*)&g_x_hi[i*4] = hh;
    *(uint2*)&g_x_lo[i*4] = ll;
}

// ---------------- QKV GEMM (mma.sync bf16 split) ----------------
#define QK_XH  0
#define QK_XL  16384
#define QK_WH  32768
#define QK_WL  40960
#define QK_BUF 49152
#define QKV_SMEM (2*QK_BUF)

__device__ __forceinline__ void qkv_stage(uint32_t sb, int sect, int m0, int kt, int tid){
    uint32_t buf = sb + (kt & 1) * QK_BUF;
    const int k0 = kt * 64;
#pragma unroll
    for (int it = 0; it < 4; it++){
        int i = tid + it*256, row = i >> 3, c = i & 7;
        uint32_t dst = (uint32_t)row*128 + ((uint32_t)(c ^ (row & 7)) << 4);
        size_t   src = (size_t)(m0 + row)*DIM + k0 + c*8;
        CP16(buf + QK_XH + dst, (const char*)g_x_hi + src*2);
        CP16(buf + QK_XL + dst, (const char*)g_x_lo + src*2);
    }
#pragma unroll
    for (int it = 0; it < 2; it++){
        int i = tid + it*256, row = i >> 3, c = i & 7;
        uint32_t dst = (uint32_t)row*128 + ((uint32_t)(c ^ (row & 7)) << 4);
        size_t   src = (size_t)(k0 + row)*NQKV + sect*64 + c*8;
        CP16(buf + QK_WH + dst, (const char*)g_w_hi + src*2);
        CP16(buf + QK_WL + dst, (const char*)g_w_lo + src*2);
    }
}

__global__ void __launch_bounds__(256) qkv_mma_kernel(){
    extern __shared__ char sm[];
    uint32_t sb = smem_u32(sm);
    const int tid = threadIdx.x, w = tid >> 5, lane = tid & 31;
    const int g = lane >> 2, tig = lane & 3;
    const int sect = blockIdx.x, m0 = blockIdx.y << 7;

    qkv_stage(sb, sect, m0, 0, tid); CP_COMMIT();
    qkv_stage(sb, sect, m0, 1, tid); CP_COMMIT();

    float acc[8][4];
#pragma unroll
    for (int j = 0; j < 8; j++){ acc[j][0]=0.f; acc[j][1]=0.f; acc[j][2]=0.f; acc[j][3]=0.f; }

    for (int kt = 0; kt < 16; kt++){
        if (kt < 15) { CP_WAIT1(); } else { CP_WAIT0(); }
        __syncthreads();
        const uint32_t buf = sb + (kt & 1) * QK_BUF;
#pragma unroll
        for (int ks = 0; ks < 4; ks++){
            uint32_t ah[4], al[4];
            LDSM4(ah, xaddr(buf + QK_XH, w*16, ks, lane));
            LDSM4(al, xaddr(buf + QK_XL, w*16, ks, lane));
#pragma unroll
            for (int npp = 0; npp < 2; npp++){
                uint32_t b0h[4], b0l[4], b1h[4], b1l[4];
                LDSM4T(b0h, xaddr(buf + QK_WH, ks*16, npp*2,   lane));
                LDSM4T(b1h, xaddr(buf + QK_WH, ks*16, npp*2+1, lane));
                LDSM4T(b0l, xaddr(buf + QK_WL, ks*16, npp*2,   lane));
                LDSM4T(b1l, xaddr(buf + QK_WL, ks*16, npp*2+1, lane));
                float* a0 = acc[npp*4]; float* a1 = acc[npp*4+1];
                float* a2 = acc[npp*4+2]; float* a3 = acc[npp*4+3];
                mma_bf16(a0, ah, b0h[0], b0h[1]); mma_bf16(a1, ah, b0h[2], b0h[3]);
                mma_bf16(a2, ah, b1h[0], b1h[1]); mma_bf16(a3, ah, b1h[2], b1h[3]);
                mma_bf16(a0, al, b0h[0], b0h[1]); mma_bf16(a1, al, b0h[2], b0h[3]);
                mma_bf16(a2, al, b1h[0], b1h[1]); mma_bf16(a3, al, b1h[2], b1h[3]);
                mma_bf16(a0, ah, b0l[0], b0l[1]); mma_bf16(a1, ah, b0l[2], b0l[3]);
                mma_bf16(a2, ah, b1l[0], b1l[1]); mma_bf16(a3, ah, b1l[2], b1l[3]);
            }
        }
        __syncthreads();
        if (kt + 2 < 16){ qkv_stage(sb, sect, m0, kt + 2, tid); CP_COMMIT(); }
    }

    const int r0 = m0 + w*16 + g;
#pragma unroll
    for (int j = 0; j < 8; j++){
        const int col = j*8 + tig*2;
        if (sect == 0){
            float2 v0; v0.x = acc[j][0]*0.125f; v0.y = acc[j][1]*0.125f;
            float2 v1; v1.x = acc[j][2]*0.125f; v1.y = acc[j][3]*0.125f;
            *(float2*)&g_q[(size_t)r0*HS + col]       = v0;
            *(float2*)&g_q[(size_t)(r0+8)*HS + col]   = v1;
        } else {
            __nv_bfloat16 h0,l0,h1,l1,h2,l2,h3,l3;
            split_bf16(acc[j][0],h0,l0); split_bf16(acc[j][1],h1,l1);
            split_bf16(acc[j][2],h2,l2); split_bf16(acc[j][3],h3,l3);
            __nv_bfloat16* dh = (sect == 1) ? g_k_hi : g_v_hi;
            __nv_bfloat16* dl = (sect == 1) ? g_k_lo : g_v_lo;
            *(uint32_t*)&dh[(size_t)r0*HS + col]     = pack2(h0,h1);
            *(uint32_t*)&dl[(size_t)r0*HS + col]     = pack2(l0,l1);
            *(uint32_t*)&dh[(size_t)(r0+8)*HS + col] = pack2(h2,h3);
            *(uint32_t*)&dl[(size_t)(r0+8)*HS + col] = pack2(l2,l3);
        }
    }
}

// ---------------- attention (mma.sync bf16 split, 16 warps, key-split) ----------------
#define SM_QH   0
#define SM_QL   16384
#define SM_BUF  32768
#define BUFSZ   65536
#define OF_KH   0
#define OF_KL   16384
#define OF_VH   32768
#define OF_VL   49152
#define SM_MASK 163840
#define ATTN_SMEM 164864
// epilogue reuse: O combine at sm[0..34815] (stride 68), lp at sm+36864

__device__ __forceinline__ void stage(uint32_t sb, int b, int k0, int t, int tid){
    uint32_t buf = sb + SM_BUF + (t & 1) * BUFSZ;
    const char* kh = (const char*)(g_k_hi + ((size_t)b*SEQ + k0)*HS);
    const char* kl = (const char*)(g_k_lo + ((size_t)b*SEQ + k0)*HS);
    const char* vh = (const char*)(g_v_hi + ((size_t)b*SEQ + k0)*HS);
    const char* vl = (const char*)(g_v_lo + ((size_t)b*SEQ + k0)*HS);
#pragma unroll
    for (int it = 0; it < 2; it++){
        int i = tid + it*512, row = i >> 3, c = i & 7;
        uint32_t dst = (uint32_t)row*128 + ((uint32_t)(c ^ (row & 7)) << 4);
        size_t   src = (size_t)row*128 + c*16;
        CP16(buf + OF_KH + dst, kh + src);
        CP16(buf + OF_KL + dst, kl + src);
        CP16(buf + OF_VH + dst, vh + src);
        CP16(buf + OF_VL + dst, vl + src);
    }
    if (tid < 32)
        CP16(sb + SM_MASK + (t & 1)*512 + tid*16, g_maskadd + (size_t)b*SEQ + k0 + tid*4);
}

__global__ void __launch_bounds__(512) attn_kernel(float* __restrict__ out){
    extern __shared__ char sm[];
    uint32_t sb = smem_u32(sm);
    const int tid = threadIdx.x, w = tid >> 5, lane = tid & 31;
    const int g = lane >> 2, tig = lane & 3;
    const int wg = w >> 3, wl = w & 7;          // key-half group, row-block
    const int kb = wg * 64;
    const int b = blockIdx.y, q0 = blockIdx.x << 7;

    stage(sb, b, 0, 0, tid);   CP_COMMIT();
    stage(sb, b, 128, 1, tid); CP_COMMIT();

    // Q (fp32, pre-scaled) -> split bf16 hi/lo into swizzled smem
#pragma unroll
    for (int it = 0; it < 2; it++){
        int ch = tid + it*512;
        int row = ch >> 3, c = ch & 7;
        const float4* qp = (const float4*)(g_q + ((size_t)b*SEQ + q0 + row)*HS + c*8);
        float4 v0 = qp[0], v1 = qp[1];
        __nv_bfloat16 h0,l0,h1,l1,h2,l2,h3,l3,h4,l4,h5,l5,h6,l6,h7,l7;
        split_bf16(v0.x,h0,l0); split_bf16(v0.y,h1,l1); split_bf16(v0.z,h2,l2); split_bf16(v0.w,h3,l3);
        split_bf16(v1.x,h4,l4); split_bf16(v1.y,h5,l5); split_bf16(v1.z,h6,l6); split_bf16(v1.w,h7,l7);
        uint4 hh; hh.x = pack2(h0,h1); hh.y = pack2(h2,h3); hh.z = pack2(h4,h5); hh.w = pack2(h6,h7);
        uint4 ll; ll.x = pack2(l0,l1); ll.y = pack2(l2,l3); ll.z = pack2(l4,l5); ll.w = pack2(l6,l7);
        uint32_t d = (uint32_t)row*128 + ((uint32_t)(c ^ (row & 7)) << 4);
        *(uint4*)(sm + SM_QH + d) = hh;
        *(uint4*)(sm + SM_QL + d) = ll;
    }
    __syncthreads();

    float o[8][4];
#pragma unroll
    for (int j = 0; j < 8; j++){ o[j][0]=0.f; o[j][1]=0.f; o[j][2]=0.f; o[j][3]=0.f; }
    float lp0 = 0.f, lp1 = 0.f;

    for (int t = 0; t < 32; t++){
        if (t < 31) { CP_WAIT1(); } else { CP_WAIT0(); }
        __syncthreads();
        const uint32_t buf = sb + SM_BUF + (t & 1)*BUFSZ;
        const char* msk = sm + SM_MASK + (t & 1)*512;

        float s[8][4];
#pragma unroll
        for (int j = 0; j < 8; j++){ s[j][0]=0.f; s[j][1]=0.f; s[j][2]=0.f; s[j][3]=0.f; }
#pragma unroll
        for (int ks = 0; ks < 4; ks++){
            uint32_t qh4[4], ql4[4];
            LDSM4(qh4, xaddr(sb + SM_QH, wl*16, ks, lane));
            LDSM4(ql4, xaddr(sb + SM_QL, wl*16, ks, lane));
#pragma unroll
            for (int pp = 0; pp < 2; pp++){
                uint32_t k0h[4], k0l[4], k1h[4], k1l[4];
                LDSM4(k0h, xaddr(buf + OF_KH, kb + (pp*2)*16,   ks, lane));
                LDSM4(k1h, xaddr(buf + OF_KH, kb + (pp*2+1)*16, ks, lane));
                LDSM4(k0l, xaddr(buf + OF_KL, kb + (pp*2)*16,   ks, lane));
                LDSM4(k1l, xaddr(buf + OF_KL, kb + (pp*2+1)*16, ks, lane));
                float* s0 = s[pp*4]; float* s1 = s[pp*4+1];
                float* s2 = s[pp*4+2]; float* s3 = s[pp*4+3];
                mma_bf16(s0, qh4, k0h[0], k0h[2]); mma_bf16(s1, qh4, k0h[1], k0h[3]);
                mma_bf16(s2, qh4, k1h[0], k1h[2]); mma_bf16(s3, qh4, k1h[1], k1h[3]);
                mma_bf16(s0, ql4, k0h[0], k0h[2]); mma_bf16(s1, ql4, k0h[1], k0h[3]);
                mma_bf16(s2, ql4, k1h[0], k1h[2]); mma_bf16(s3, ql4, k1h[1], k1h[3]);
                mma_bf16(s0, qh4, k0l[0], k0l[2]); mma_bf16(s1, qh4, k0l[1], k0l[3]);
                mma_bf16(s2, qh4, k1l[0], k1l[2]); mma_bf16(s3, qh4, k1l[1], k1l[3]);
            }
        }

        uint32_t ph[4][4], pl[4][4];
#pragma unroll
        for (int j = 0; j < 8; j++){
            float2 mv = *(const float2*)(msk + (kb + j*8 + 2*tig)*4);
            float p0 = __expf(s[j][0] + mv.x - OFFS);
            float p1 = __expf(s[j][1] + mv.y - OFFS);
            float p2 = __expf(s[j][2] + mv.x - OFFS);
            float p3 = __expf(s[j][3] + mv.y - OFFS);
            lp0 += p0 + p1; lp1 += p2 + p3;
            __nv_bfloat16 a0,b0,a1,b1,a2,b2,a3,b3;
            split_bf16(p0,a0,b0); split_bf16(p1,a1,b1);
            split_bf16(p2,a2,b2); split_bf16(p3,a3,b3);
            int kk = j >> 1, od = (j & 1) << 1;
            ph[kk][od] = pack2(a0,a1); ph[kk][od+1] = pack2(a2,a3);
            pl[kk][od] = pack2(b0,b1); pl[kk][od+1] = pack2(b2,b3);
        }

#pragma unroll
        for (int kk = 0; kk < 4; kk++){
#pragma unroll
            for (int dpp = 0; dpp < 2; dpp++){
                uint32_t v0h[4], v0l[4], v1h[4], v1l[4];
                LDSM4T(v0h, xaddr(buf + OF_VH, kb + kk*16, dpp*2,   lane));
                LDSM4T(v1h, xaddr(buf + OF_VH, kb + kk*16, dpp*2+1, lane));
                LDSM4T(v0l, xaddr(buf + OF_VL, kb + kk*16, dpp*2,   lane));
                LDSM4T(v1l, xaddr(buf + OF_VL, kb + kk*16, dpp*2+1, lane));
                float* o0 = o[dpp*4]; float* o1 = o[dpp*4+1];
                float* o2 = o[dpp*4+2]; float* o3 = o[dpp*4+3];
                mma_bf16(o0, ph[kk], v0h[0], v0h[1]); mma_bf16(o1, ph[kk], v0h[2], v0h[3]);
                mma_bf16(o2, ph[kk], v1h[0], v1h[1]); mma_bf16(o3, ph[kk], v1h[2], v1h[3]);
                mma_bf16(o0, pl[kk], v0h[0], v0h[1]); mma_bf16(o1, pl[kk], v0h[2], v0h[3]);
                mma_bf16(o2, pl[kk], v1h[0], v1h[1]); mma_bf16(o3, pl[kk], v1h[2], v1h[3]);
                mma_bf16(o0, ph[kk], v0l[0], v0l[1]); mma_bf16(o1, ph[kk], v0l[2], v0l[3]);
                mma_bf16(o2, ph[kk], v1l[0], v1l[1]); mma_bf16(o3, ph[kk], v1l[2], v1l[3]);
            }
        }
        __syncthreads();
        if (t + 2 < 32){ stage(sb, b, (t+2)*128, t+2, tid); CP_COMMIT(); }
    }

    // reduce lp within quad (keys dim)
    lp0 += __shfl_xor_sync(0xffffffffu, lp0, 1);
    lp0 += __shfl_xor_sync(0xffffffffu, lp0, 2);
    lp1 += __shfl_xor_sync(0xffffffffu, lp1, 1);
    lp1 += __shfl_xor_sync(0xffffffffu, lp1, 2);

    // combine the two key-half warp-groups via smem (Q area is dead now)
    float* Osm = (float*)sm;                 // [128][68] fp32
    float* Lsm = (float*)(sm + 36864);       // [128] fp32
    const int r0 = wl*16 + g, r1 = r0 + 8;
    if (wg == 1){
#pragma unroll
        for (int j = 0; j < 8; j++){
            Osm[r0*68 + j*8 + 2*tig]     = o[j][0];
            Osm[r0*68 + j*8 + 2*tig + 1] = o[j][1];
            Osm[r1*68 + j*8 + 2*tig]     = o[j][2];
            Osm[r1*68 + j*8 + 2*tig + 1] = o[j][3];
        }
        if (tig == 0){ Lsm[r0] = lp0; Lsm[r1] = lp1; }
    }
    __syncthreads();
    if (wg == 0){
        float i0 = 1.0f / (lp0 + Lsm[r0]);
        float i1 = 1.0f / (lp1 + Lsm[r1]);
        float* out0 = out + ((size_t)b*SEQ + q0 + r0)*HS;
        float* out1 = out + ((size_t)b*SEQ + q0 + r1)*HS;
#pragma unroll
        for (int j = 0; j < 8; j++){
            const int col = j*8 + 2*tig;
            float2 v0;
            v0.x = (o[j][0] + Osm[r0*68 + col])     * i0;
            v0.y = (o[j][1] + Osm[r0*68 + col + 1]) * i0;
            float2 v1;
            v1.x = (o[j][2] + Osm[r1*68 + col])     * i1;
            v1.y = (o[j][3] + Osm[r1*68 + col + 1]) * i1;
            *(float2*)(out0 + col) = v0;
            *(float2*)(out1 + col) = v1;
        }
    }
}

extern "C" void kernel_launch(void* const* d_in, const int* in_sizes, int n_in,
                              void* d_out, int out_size){
    const float*         x    = (const float*)d_in[0];
    const unsigned char* mask = (const unsigned char*)d_in[1];
    const float*         W    = (const float*)d_in[2];
    float*               out  = (float*)d_out;
    (void)in_sizes; (void)n_in; (void)out_size;

    prep_kernel<<<256, 256>>>(mask, W);
    xconv_kernel<<<(BATCH*SEQ*DIM)/(256*4), 256>>>(x);
    cudaFuncSetAttribute(qkv_mma_kernel, cudaFuncAttributeMaxDynamicSharedMemorySize, QKV_SMEM);
    qkv_mma_kernel<<<dim3(3, (BATCH*SEQ)/128), 256, QKV_SMEM>>>();
    cudaFuncSetAttribute(attn_kernel, cudaFuncAttributeMaxDynamicSharedMemorySize, ATTN_SMEM);
    attn_kernel<<<dim3(SEQ/128, BATCH), 512, ATTN_SMEM>>>(out);
}